// round 10
// baseline (speedup 1.0000x reference)
#include <cuda_runtime.h>
#include <cstdint>

#define P_ 4096
#define PN_ 32
#define PE_ 128
#define B_ 4
#define M_ 1024
#define ME_ 16384
#define IN_ 64
#define HP_ 256
#define HP4_ 64
#define RD_ 256
#define HM_ 512
#define OUT_ 16
#define RTOT_ (IN_+HP_+HP4_)   // 384
#define EPS_ 1e-5f
#define SLOPE_ 0.01f

// ---------------- scratch ----------------
__device__ float g_R  [(size_t)P_*RTOT_];      // readout concat  [4096,384]
__device__ float g_NF [(size_t)P_*RD_];        // node feats      [4096,256]
__device__ float g_NFa[(size_t)B_*M_*RD_];     // mesh-agg node feats
__device__ float g_HM [(size_t)B_*M_*HM_];     // mesh conv1 pre-norm
__device__ float g_HMa[(size_t)B_*M_*HM_];     // mesh-agg (normed) h1
__device__ float g_HM2[(size_t)B_*M_*HM_];     // mesh conv2 pre-norm
__device__ float g_mins[B_*M_];
__device__ int   g_rowstart[B_*M_];
__device__ int   g_srcs[B_*ME_];
__device__ float g_wgt [B_*ME_];
// accumulator pool (zeroed by k_mesh_csr):
//  [0,2048) s1 L1  [2048,4096) s2 L1  [4096,6144) s1 L2
//  [6144,8192) s2 L2  [8192,12288) block readout
#define POOL_W 12288
__device__ float g_pool[POOL_W];

// ---------------- tf32 helpers ----------------
__device__ __forceinline__ uint32_t f2tf32(float f) {
    uint32_t u;
    asm("cvt.rna.tf32.f32 %0, %1;" : "=r"(u) : "f"(f));
    return u;
}
__device__ __forceinline__ uint32_t smem_u32(const void* p) {
    return static_cast<uint32_t>(__cvta_generic_to_shared(p));
}
__device__ __forceinline__ void ldsm_x4(uint32_t& r0, uint32_t& r1,
                                        uint32_t& r2, uint32_t& r3, uint32_t addr) {
    asm volatile("ldmatrix.sync.aligned.m8n8.x4.shared.b16 {%0,%1,%2,%3}, [%4];\n"
                 : "=r"(r0), "=r"(r1), "=r"(r2), "=r"(r3) : "r"(addr));
}
__device__ __forceinline__ void mma_tf32(float* c, const uint32_t* a,
                                         uint32_t b0, uint32_t b1) {
    asm volatile(
        "mma.sync.aligned.m16n8k8.row.col.f32.tf32.tf32.f32 "
        "{%0,%1,%2,%3}, {%4,%5,%6,%7}, {%8,%9}, {%0,%1,%2,%3};\n"
        : "+f"(c[0]), "+f"(c[1]), "+f"(c[2]), "+f"(c[3])
        : "r"(a[0]), "r"(a[1]), "r"(a[2]), "r"(a[3]), "r"(b0), "r"(b1));
}
__device__ __forceinline__ float red8(float v) {
    v += __shfl_xor_sync(0xffffffffu, v, 4);
    v += __shfl_xor_sync(0xffffffffu, v, 8);
    v += __shfl_xor_sync(0xffffffffu, v, 16);
    return v;
}
__device__ __forceinline__ float lrelu_f(float x) { return x >= 0.f ? x : SLOPE_*x; }

// ============== fused patch phase: one CTA = 2 patches =====================
#define SMW_TOTAL 28672
#define SMB_PATCH (SMW_TOTAL*4)

__global__ void __launch_bounds__(256)
k_patch_all(const float* __restrict__ feats, const int* __restrict__ src,
            const int* __restrict__ dst, const float* __restrict__ ew,
            const float* __restrict__ Wp1, const float* __restrict__ Wp2,
            const float* __restrict__ g1g, const float* __restrict__ g1b,
            const float* __restrict__ g1a, const float* __restrict__ g2g,
            const float* __restrict__ g2b, const float* __restrict__ g2a)
{
    extern __shared__ uint32_t S[];
    float*    WTf  = (float*)S;                  // [64][36] fp32 build
    uint32_t* WT   = S;                          // same, tf32 after cvt
    float*    outs = (float*)(S + 2304);         // 64
    float*    ins  = (float*)(S + 2368);         // 64
    int*      cnt  = (int*)  (S + 2432);         // 128
    uint32_t* Xs   = S + 2560;                   // [64][72] tf32
    uint32_t* A1   = S + 7168;                   // [64][68] tf32
    uint32_t* Bs2  = S + 2560;                   // [128][72] tf32
    uint32_t* B1   = S + 11776;                  // [64][264]
    uint32_t* As2  = S + 11776;                  // [64][260]
    uint32_t* H2s  = S + 11776;                  // [64][72]

    const int t    = threadIdx.x;
    const int blk  = blockIdx.x;
    const int lane = t & 31;
    const int wid  = t >> 5;

    // ---- phase 0: zero WT/cnt, load X (tf32), load Wp1 ----
    #pragma unroll
    for (int i = t; i < 2304; i += 256) WTf[i] = 0.f;
    if (t < 128) cnt[t] = 0;
    {
        const float4* f4 = (const float4*)(feats + (size_t)blk*64*IN_);
        #pragma unroll
        for (int i = 0; i < 4; i++) {
            int lin = t + i*256;
            int lr = lin >> 4, cq = lin & 15;
            float4 v = f4[lin];
            *(uint4*)(Xs + lr*72 + cq*4) =
                make_uint4(f2tf32(v.x), f2tf32(v.y), f2tf32(v.z), f2tf32(v.w));
        }
        const float4* w4 = (const float4*)Wp1;
        #pragma unroll
        for (int i = 0; i < 16; i++) {
            int lin = t + i*256;
            int k = lin >> 6, nq = lin & 63;
            float4 v = w4[lin];
            *(uint4*)(B1 + k*264 + nq*4) =
                make_uint4(f2tf32(v.x), f2tf32(v.y), f2tf32(v.z), f2tf32(v.w));
        }
    }
    __syncthreads();

    // ---- phase 1: dense normalized adjacency (fp32 -> tf32 in place) ----
    {
        int q = t >> 7, e = t & 127;
        int p = blk*2 + q;
        int s = src[p*PE_ + e], d = dst[p*PE_ + e];
        atomicAdd(&WTf[(q*32 + d)*36 + s], ew[p*PE_ + e]);
        atomicAdd(&cnt[q*PN_ + s], 1);
        atomicAdd(&cnt[64 + q*PN_ + d], 1);
    }
    __syncthreads();
    if (t < 64) {
        outs[t] = rsqrtf(fmaxf((float)cnt[t], 1.f));
        ins[t]  = rsqrtf(fmaxf((float)cnt[64 + t], 1.f));
    }
    __syncthreads();
    for (int idx = t; idx < 2304; idx += 256) {
        int row = idx / 36;
        int s = idx - row*36;
        if (s < 32) {
            int q = row >> 5, d = row & 31;
            float v = WTf[idx] * ins[q*32 + d] * outs[q*32 + s];
            WT[idx] = f2tf32(v);
        }
    }
    // r0 readout
    if (t < 128) {
        int q = t >> 6, col = t & 63;
        float s1 = 0.f;
        #pragma unroll
        for (int s = 0; s < PN_; s++)
            s1 += __uint_as_float(Xs[(q*32 + s)*72 + col]);
        g_R[(size_t)(blk*2 + q)*RTOT_ + col] = s1 * (1.f/PN_);
    }
    __syncthreads();

    const int wm  = (wid >> 2) * 32;
    const int q2  = wid >> 2;
    const int arow = wm + (lane & 15);
    const int acol = (lane >> 4) * 4;
    const int bk0  = lane & 3;
    const int r0   = lane >> 2;
    const int c0   = (lane & 3) * 2;

    // ---- phase 2: Xa = Wt @ X via mma -> A1 (tf32) ----
    {
        const int wn2p = (wid & 3) * 16;
        const int bn2  = wn2p + (lane >> 2);
        float cA[2][2][4];
        #pragma unroll
        for (int i = 0; i < 2; i++)
            #pragma unroll
            for (int j = 0; j < 2; j++)
                #pragma unroll
                for (int qq = 0; qq < 4; qq++) cA[i][j][qq] = 0.f;
        #pragma unroll
        for (int ks = 0; ks < 4; ks++) {
            uint32_t a[2][4];
            #pragma unroll
            for (int i = 0; i < 2; i++) {
                uint32_t addr = smem_u32(WT + (arow + i*16)*36 + ks*8 + acol);
                ldsm_x4(a[i][0], a[i][1], a[i][2], a[i][3], addr);
            }
            uint32_t b0[2], b1v[2];
            #pragma unroll
            for (int j = 0; j < 2; j++) {
                b0[j]  = Xs[(q2*32 + ks*8 + bk0)*72 + bn2 + j*8];
                b1v[j] = Xs[(q2*32 + ks*8 + 4 + bk0)*72 + bn2 + j*8];
            }
            #pragma unroll
            for (int i = 0; i < 2; i++)
                #pragma unroll
                for (int j = 0; j < 2; j++)
                    mma_tf32(cA[i][j], a[i], b0[j], b1v[j]);
        }
        #pragma unroll
        for (int i = 0; i < 2; i++)
            #pragma unroll
            for (int j = 0; j < 2; j++) {
                uint32_t* d0 = A1 + (wm + i*16 + r0)*68 + wn2p + j*8 + c0;
                *(uint2*)(d0)        = make_uint2(f2tf32(cA[i][j][0]), f2tf32(cA[i][j][1]));
                *(uint2*)(d0 + 8*68) = make_uint2(f2tf32(cA[i][j][2]), f2tf32(cA[i][j][3]));
            }
    }
    __syncthreads();

    // ---- phase 3: conv1 mma: [64,64] @ [64,256] ----
    const int wn  = (wid & 3) * 64;
    const int bn0 = wn + (lane >> 2);

    float c1[2][8][4];
    #pragma unroll
    for (int i = 0; i < 2; i++)
        #pragma unroll
        for (int j = 0; j < 8; j++)
            #pragma unroll
            for (int q = 0; q < 4; q++) c1[i][j][q] = 0.f;

    #pragma unroll
    for (int ks = 0; ks < 8; ks++) {
        uint32_t a[2][4];
        #pragma unroll
        for (int i = 0; i < 2; i++) {
            uint32_t addr = smem_u32(A1 + (arow + i*16)*68 + ks*8 + acol);
            ldsm_x4(a[i][0], a[i][1], a[i][2], a[i][3], addr);
        }
        uint32_t b0[8], b1v[8];
        #pragma unroll
        for (int j = 0; j < 8; j++) {
            b0[j]  = B1[(ks*8 + bk0)*264 + bn0 + j*8];
            b1v[j] = B1[(ks*8 + 4 + bk0)*264 + bn0 + j*8];
        }
        #pragma unroll
        for (int i = 0; i < 2; i++)
            #pragma unroll
            for (int j = 0; j < 8; j++)
                mma_tf32(c1[i][j], a[i], b0[j], b1v[j]);
    }
    __syncthreads();

    // ---- phase 4: GraphNorm + lrelu + r1; H1 -> As2 (tf32) ----
    {
        const int pat = blk*2 + q2;
        const float inv32 = 1.f / 32.f;
        #pragma unroll
        for (int j = 0; j < 8; j++) {
            int ca = wn + j*8 + c0;
            float va0=c1[0][j][0], va1=c1[0][j][2], va2=c1[1][j][0], va3=c1[1][j][2];
            float vb0=c1[0][j][1], vb1=c1[0][j][3], vb2=c1[1][j][1], vb3=c1[1][j][3];
            float ma = red8(va0+va1+va2+va3) * inv32;
            float mb = red8(vb0+vb1+vb2+vb3) * inv32;
            float ama = __ldg(&g1a[ca])   * ma;
            float amb = __ldg(&g1a[ca+1]) * mb;
            float da0=va0-ama, da1=va1-ama, da2=va2-ama, da3=va3-ama;
            float db0=vb0-amb, db1=vb1-amb, db2=vb2-amb, db3=vb3-amb;
            float qa = red8(da0*da0+da1*da1+da2*da2+da3*da3);
            float qb = red8(db0*db0+db1*db1+db2*db2+db3*db3);
            float ia = rsqrtf(qa*inv32 + EPS_);
            float ib = rsqrtf(qb*inv32 + EPS_);
            float ga = __ldg(&g1g[ca]),   ba = __ldg(&g1b[ca]);
            float gb = __ldg(&g1g[ca+1]), bb = __ldg(&g1b[ca+1]);
            float ha0=lrelu_f(ga*da0*ia+ba), ha1=lrelu_f(ga*da1*ia+ba);
            float ha2=lrelu_f(ga*da2*ia+ba), ha3=lrelu_f(ga*da3*ia+ba);
            float hb0=lrelu_f(gb*db0*ib+bb), hb1=lrelu_f(gb*db1*ib+bb);
            float hb2=lrelu_f(gb*db2*ib+bb), hb3=lrelu_f(gb*db3*ib+bb);
            uint32_t* dst0 = As2 + (wm + r0)*260 + wn + j*8 + c0;
            *(uint2*)(dst0)          = make_uint2(f2tf32(ha0), f2tf32(hb0));
            *(uint2*)(dst0 + 8*260)  = make_uint2(f2tf32(ha1), f2tf32(hb1));
            *(uint2*)(dst0 + 16*260) = make_uint2(f2tf32(ha2), f2tf32(hb2));
            *(uint2*)(dst0 + 24*260) = make_uint2(f2tf32(ha3), f2tf32(hb3));
            float ra = red8(ha0+ha1+ha2+ha3) * inv32;
            float rb = red8(hb0+hb1+hb2+hb3) * inv32;
            if (r0 == 0) {
                g_R[(size_t)pat*RTOT_ + IN_ + ca]     = ra;
                g_R[(size_t)pat*RTOT_ + IN_ + ca + 1] = rb;
            }
        }
    }
    __syncthreads();

    // ---- phase 5: conv2 mma: [64,256] @ [256,64], K in 2 chunks ----
    const int wn2  = (wid & 3) * 16;
    const int bn02 = wn2 + (lane >> 2);
    float c2[2][2][4];
    #pragma unroll
    for (int i = 0; i < 2; i++)
        #pragma unroll
        for (int j = 0; j < 2; j++)
            #pragma unroll
            for (int q = 0; q < 4; q++) c2[i][j][q] = 0.f;

    #pragma unroll
    for (int ch = 0; ch < 2; ch++) {
        const float4* w4 = (const float4*)(Wp2 + (size_t)ch*128*HP4_);
        #pragma unroll
        for (int i = 0; i < 8; i++) {
            int lin = t + i*256;
            int k = lin >> 4, nq = lin & 15;
            float4 v = w4[lin];
            *(uint4*)(Bs2 + k*72 + nq*4) =
                make_uint4(f2tf32(v.x), f2tf32(v.y), f2tf32(v.z), f2tf32(v.w));
        }
        __syncthreads();
        #pragma unroll
        for (int ks = 0; ks < 16; ks++) {
            uint32_t a[2][4];
            #pragma unroll
            for (int i = 0; i < 2; i++) {
                uint32_t addr = smem_u32(As2 + (arow + i*16)*260 + ch*128 + ks*8 + acol);
                ldsm_x4(a[i][0], a[i][1], a[i][2], a[i][3], addr);
            }
            uint32_t b0[2], b1v[2];
            #pragma unroll
            for (int j = 0; j < 2; j++) {
                b0[j]  = Bs2[(ks*8 + bk0)*72 + bn02 + j*8];
                b1v[j] = Bs2[(ks*8 + 4 + bk0)*72 + bn02 + j*8];
            }
            #pragma unroll
            for (int i = 0; i < 2; i++)
                #pragma unroll
                for (int j = 0; j < 2; j++)
                    mma_tf32(c2[i][j], a[i], b0[j], b1v[j]);
        }
        __syncthreads();
    }

    // ---- phase 6: H2 -> smem (tf32, pitch 72) ----
    #pragma unroll
    for (int i = 0; i < 2; i++)
        #pragma unroll
        for (int j = 0; j < 2; j++) {
            uint32_t* d0 = H2s + (wm + i*16 + r0)*72 + wn2 + j*8 + c0;
            *(uint2*)(d0)        = make_uint2(f2tf32(c2[i][j][0]), f2tf32(c2[i][j][1]));
            *(uint2*)(d0 + 8*72) = make_uint2(f2tf32(c2[i][j][2]), f2tf32(c2[i][j][3]));
        }
    __syncthreads();

    // ---- phase 7: agg via mma (Wt @ H2) + GraphNorm + lrelu + r2 ----
    {
        const int wn7 = (wid & 3) * 16;
        const int bn7 = wn7 + (lane >> 2);
        float c7[2][2][4];
        #pragma unroll
        for (int i = 0; i < 2; i++)
            #pragma unroll
            for (int j = 0; j < 2; j++)
                #pragma unroll
                for (int qq = 0; qq < 4; qq++) c7[i][j][qq] = 0.f;
        #pragma unroll
        for (int ks = 0; ks < 4; ks++) {
            uint32_t a[2][4];
            #pragma unroll
            for (int i = 0; i < 2; i++) {
                uint32_t addr = smem_u32(WT + (arow + i*16)*36 + ks*8 + acol);
                ldsm_x4(a[i][0], a[i][1], a[i][2], a[i][3], addr);
            }
            uint32_t b0[2], b1v[2];
            #pragma unroll
            for (int j = 0; j < 2; j++) {
                b0[j]  = H2s[(q2*32 + ks*8 + bk0)*72 + bn7 + j*8];
                b1v[j] = H2s[(q2*32 + ks*8 + 4 + bk0)*72 + bn7 + j*8];
            }
            #pragma unroll
            for (int i = 0; i < 2; i++)
                #pragma unroll
                for (int j = 0; j < 2; j++)
                    mma_tf32(c7[i][j], a[i], b0[j], b1v[j]);
        }
        const int pat = blk*2 + q2;
        const float inv32 = 1.f / 32.f;
        #pragma unroll
        for (int j = 0; j < 2; j++) {
            int ca = wn7 + j*8 + c0;
            float va0=c7[0][j][0], va1=c7[0][j][2], va2=c7[1][j][0], va3=c7[1][j][2];
            float vb0=c7[0][j][1], vb1=c7[0][j][3], vb2=c7[1][j][1], vb3=c7[1][j][3];
            float ma = red8(va0+va1+va2+va3) * inv32;
            float mb = red8(vb0+vb1+vb2+vb3) * inv32;
            float ama = __ldg(&g2a[ca])   * ma;
            float amb = __ldg(&g2a[ca+1]) * mb;
            float da0=va0-ama, da1=va1-ama, da2=va2-ama, da3=va3-ama;
            float db0=vb0-amb, db1=vb1-amb, db2=vb2-amb, db3=vb3-amb;
            float qa = red8(da0*da0+da1*da1+da2*da2+da3*da3);
            float qb = red8(db0*db0+db1*db1+db2*db2+db3*db3);
            float ia = rsqrtf(qa*inv32 + EPS_);
            float ib = rsqrtf(qb*inv32 + EPS_);
            float ga = __ldg(&g2g[ca]),   ba = __ldg(&g2b[ca]);
            float gb = __ldg(&g2g[ca+1]), bb = __ldg(&g2b[ca+1]);
            float ra = red8(lrelu_f(ga*da0*ia+ba) + lrelu_f(ga*da1*ia+ba)
                          + lrelu_f(ga*da2*ia+ba) + lrelu_f(ga*da3*ia+ba)) * inv32;
            float rb = red8(lrelu_f(gb*db0*ib+bb) + lrelu_f(gb*db1*ib+bb)
                          + lrelu_f(gb*db2*ib+bb) + lrelu_f(gb*db3*ib+bb)) * inv32;
            if (r0 == 0) {
                g_R[(size_t)pat*RTOT_ + IN_ + HP_ + ca]     = ra;
                g_R[(size_t)pat*RTOT_ + IN_ + HP_ + ca + 1] = rb;
            }
        }
    }
}

// ---------------- tf32 GEMM (mesh); optional column-stats epilogue ---------
template<int BM, int BN, bool STATS>
__global__ void __launch_bounds__(256)
gemm_tf32(const float* __restrict__ A, const float* __restrict__ B,
          float* __restrict__ C, int Mdim, int Ndim, int Kdim,
          float* __restrict__ s1p, float* __restrict__ s2p)
{
    constexpr int BK  = 32;
    constexpr int WM  = 32;
    constexpr int WN  = BN / 2;
    constexpr int MT  = WM / 16;
    constexpr int NT  = WN / 8;
    constexpr int ASR = BK + 4;
    constexpr int BSR = BN + 8;
    constexpr int ASZ = BM * ASR;
    constexpr int BSZ = BK * BSR;
    constexpr int ALD = BM * BK / 4 / 256;
    constexpr int BLD = BK * BN / 4 / 256;

    extern __shared__ uint32_t sm_[];
    uint32_t* As = sm_;
    uint32_t* Bs = sm_ + 2 * ASZ;

    const int tid  = threadIdx.x;
    const int lane = tid & 31;
    const int wid  = tid >> 5;
    const int nblk = Ndim / BN;
    const int bx = blockIdx.x % nblk;
    const int by = blockIdx.x / nblk;
    const float* Ab = A + (size_t)by * BM * Kdim;
    const float* Bb = B + (size_t)bx * BN;

    const int wm = (wid >> 1) * WM;
    const int wn = (wid & 1) * WN;

    float c[MT][NT][4];
    #pragma unroll
    for (int i = 0; i < MT; i++)
        #pragma unroll
        for (int j = 0; j < NT; j++)
            #pragma unroll
            for (int q = 0; q < 4; q++) c[i][j][q] = 0.f;

    float4 pa[ALD], pb[BLD];

    auto ldgA = [&](int k0) {
        #pragma unroll
        for (int i = 0; i < ALD; i++) {
            int lin = tid + i * 256;
            int row = lin >> 3;
            int kq  = lin & 7;
            pa[i] = *(const float4*)(Ab + (size_t)row * Kdim + k0 + kq * 4);
        }
    };
    auto ldgB = [&](int k0) {
        #pragma unroll
        for (int i = 0; i < BLD; i++) {
            int lin = tid + i * 256;
            int kr = lin / (BN / 4);
            int nq = lin % (BN / 4);
            pb[i] = *(const float4*)(Bb + (size_t)(k0 + kr) * Ndim + nq * 4);
        }
    };
    auto stsA = [&](int buf) {
        uint32_t* base = As + buf * ASZ;
        #pragma unroll
        for (int i = 0; i < ALD; i++) {
            int lin = tid + i * 256;
            int row = lin >> 3;
            int kq  = lin & 7;
            *(uint4*)(base + row * ASR + kq * 4) =
                make_uint4(f2tf32(pa[i].x), f2tf32(pa[i].y),
                           f2tf32(pa[i].z), f2tf32(pa[i].w));
        }
    };
    auto stsB = [&](int buf) {
        uint32_t* base = Bs + buf * BSZ;
        #pragma unroll
        for (int i = 0; i < BLD; i++) {
            int lin = tid + i * 256;
            int kr = lin / (BN / 4);
            int nq = lin % (BN / 4);
            *(uint4*)(base + kr * BSR + nq * 4) =
                make_uint4(f2tf32(pb[i].x), f2tf32(pb[i].y),
                           f2tf32(pb[i].z), f2tf32(pb[i].w));
        }
    };

    const int arow = wm + (lane & 15);
    const int acol = (lane >> 4) * 4;
    const int bn0  = wn + (lane >> 2);
    const int bk0  = lane & 3;

    auto compute = [&](int buf) {
        uint32_t* Abs = As + buf * ASZ;
        uint32_t* Bbs = Bs + buf * BSZ;
        #pragma unroll
        for (int ks = 0; ks < 4; ks++) {
            uint32_t a[MT][4];
            #pragma unroll
            for (int i = 0; i < MT; i++) {
                uint32_t addr = smem_u32(Abs + (arow + i * 16) * ASR + ks * 8 + acol);
                ldsm_x4(a[i][0], a[i][1], a[i][2], a[i][3], addr);
            }
            uint32_t b0[NT], b1[NT];
            #pragma unroll
            for (int j = 0; j < NT; j++) {
                b0[j] = Bbs[(ks * 8 + bk0) * BSR + bn0 + j * 8];
                b1[j] = Bbs[(ks * 8 + 4 + bk0) * BSR + bn0 + j * 8];
            }
            #pragma unroll
            for (int i = 0; i < MT; i++)
                #pragma unroll
                for (int j = 0; j < NT; j++)
                    mma_tf32(c[i][j], a[i], b0[j], b1[j]);
        }
    };

    const int NKT = Kdim / BK;
    ldgA(0); ldgB(0);
    stsA(0); stsB(0);
    __syncthreads();
    for (int kt = 0; kt < NKT; kt++) {
        if (kt + 1 < NKT) { ldgA((kt + 1) * BK); ldgB((kt + 1) * BK); }
        compute(kt & 1);
        if (kt + 1 < NKT) { stsA((kt + 1) & 1); stsB((kt + 1) & 1); }
        __syncthreads();
    }

    float* Cb = C + (size_t)(by * BM + wm) * Ndim + (size_t)bx * BN + wn;
    const int r0 = lane >> 2;
    const int c0 = (lane & 3) * 2;
    #pragma unroll
    for (int i = 0; i < MT; i++)
        #pragma unroll
        for (int j = 0; j < NT; j++) {
            *(float2*)(Cb + (size_t)(i * 16 + r0) * Ndim + j * 8 + c0) =
                make_float2(c[i][j][0], c[i][j][1]);
            *(float2*)(Cb + (size_t)(i * 16 + r0 + 8) * Ndim + j * 8 + c0) =
                make_float2(c[i][j][2], c[i][j][3]);
        }

    if constexpr (STATS) {
        const int b = (by * BM) / M_;
        #pragma unroll
        for (int j = 0; j < NT; j++) {
            int gcol = bx * BN + wn + j * 8 + c0;
            float va0=c[0][j][0], va1=c[0][j][2], va2=c[1][j][0], va3=c[1][j][2];
            float vb0=c[0][j][1], vb1=c[0][j][3], vb2=c[1][j][1], vb3=c[1][j][3];
            float sa = red8(va0+va1+va2+va3);
            float sb = red8(vb0+vb1+vb2+vb3);
            float qa = red8(va0*va0+va1*va1+va2*va2+va3*va3);
            float qb = red8(vb0*vb0+vb1*vb1+vb2*vb2+vb3*vb3);
            if (r0 == 0) {
                atomicAdd(&s1p[b*HM_ + gcol],     sa);
                atomicAdd(&s1p[b*HM_ + gcol + 1], sb);
                atomicAdd(&s2p[b*HM_ + gcol],     qa);
                atomicAdd(&s2p[b*HM_ + gcol + 1], qb);
            }
        }
    }
}

// -------- embed GEMM with fused InstanceNorm + lrelu epilogue --------------
__global__ void __launch_bounds__(256)
gemm_embed_in(const float* __restrict__ A, const float* __restrict__ B,
              float* __restrict__ NF)
{
    constexpr int BM = 64, BN = 256, BK = 32, Kdim = RTOT_, Ndim = RD_;
    constexpr int NT = 8, MT = 2;
    constexpr int ASR = 36, BSR = 264;
    constexpr int ASZ = BM * ASR;
    constexpr int BSZ = BK * BSR;

    extern __shared__ uint32_t sm_[];
    uint32_t* As = sm_;
    uint32_t* Bs = sm_ + 2 * ASZ;

    const int tid  = threadIdx.x;
    const int lane = tid & 31;
    const int wid  = tid >> 5;
    const int by = blockIdx.x;
    const float* Ab = A + (size_t)by * BM * Kdim;

    const int wm = (wid >> 2) * 32;
    const int wn = (wid & 3) * 64;

    float c[MT][NT][4];
    #pragma unroll
    for (int i = 0; i < MT; i++)
        #pragma unroll
        for (int j = 0; j < NT; j++)
            #pragma unroll
            for (int q = 0; q < 4; q++) c[i][j][q] = 0.f;

    float4 pa[2], pb[8];
    auto ldgA = [&](int k0) {
        #pragma unroll
        for (int i = 0; i < 2; i++) {
            int lin = tid + i * 256;
            int row = lin >> 3, kq = lin & 7;
            pa[i] = *(const float4*)(Ab + (size_t)row * Kdim + k0 + kq * 4);
        }
    };
    auto ldgB = [&](int k0) {
        #pragma unroll
        for (int i = 0; i < 8; i++) {
            int lin = tid + i * 256;
            int kr = lin >> 6, nq = lin & 63;
            pb[i] = *(const float4*)(B + (size_t)(k0 + kr) * Ndim + nq * 4);
        }
    };
    auto stsA = [&](int buf) {
        uint32_t* base = As + buf * ASZ;
        #pragma unroll
        for (int i = 0; i < 2; i++) {
            int lin = tid + i * 256;
            int row = lin >> 3, kq = lin & 7;
            *(uint4*)(base + row * ASR + kq * 4) =
                make_uint4(f2tf32(pa[i].x), f2tf32(pa[i].y),
                           f2tf32(pa[i].z), f2tf32(pa[i].w));
        }
    };
    auto stsB = [&](int buf) {
        uint32_t* base = Bs + buf * BSZ;
        #pragma unroll
        for (int i = 0; i < 8; i++) {
            int lin = tid + i * 256;
            int kr = lin >> 6, nq = lin & 63;
            *(uint4*)(base + kr * BSR + nq * 4) =
                make_uint4(f2tf32(pb[i].x), f2tf32(pb[i].y),
                           f2tf32(pb[i].z), f2tf32(pb[i].w));
        }
    };

    const int arow = wm + (lane & 15);
    const int acol = (lane >> 4) * 4;
    const int bn0  = wn + (lane >> 2);
    const int bk0  = lane & 3;

    auto compute = [&](int buf) {
        uint32_t* Abs = As + buf * ASZ;
        uint32_t* Bbs = Bs + buf * BSZ;
        #pragma unroll
        for (int ks = 0; ks < 4; ks++) {
            uint32_t a[MT][4];
            #pragma unroll
            for (int i = 0; i < MT; i++) {
                uint32_t addr = smem_u32(Abs + (arow + i * 16) * ASR + ks * 8 + acol);
                ldsm_x4(a[i][0], a[i][1], a[i][2], a[i][3], addr);
            }
            uint32_t b0[NT], b1[NT];
            #pragma unroll
            for (int j = 0; j < NT; j++) {
                b0[j] = Bbs[(ks * 8 + bk0) * BSR + bn0 + j * 8];
                b1[j] = Bbs[(ks * 8 + 4 + bk0) * BSR + bn0 + j * 8];
            }
            #pragma unroll
            for (int i = 0; i < MT; i++)
                #pragma unroll
                for (int j = 0; j < NT; j++)
                    mma_tf32(c[i][j], a[i], b0[j], b1[j]);
        }
    };

    const int NKT = Kdim / BK;
    ldgA(0); ldgB(0);
    stsA(0); stsB(0);
    __syncthreads();
    for (int kt = 0; kt < NKT; kt++) {
        if (kt + 1 < NKT) { ldgA((kt + 1) * BK); ldgB((kt + 1) * BK); }
        compute(kt & 1);
        if (kt + 1 < NKT) { stsA((kt + 1) & 1); stsB((kt + 1) & 1); }
        __syncthreads();
    }
    __syncthreads();

    float* Rsum = (float*)sm_;
    float* Rsq  = (float*)sm_ + 256;
    const int r0 = lane >> 2;
    const int c0 = (lane & 3) * 2;

    #pragma unroll
    for (int i = 0; i < MT; i++) {
        #pragma unroll
        for (int h = 0; h < 2; h++) {
            float s = 0.f, q = 0.f;
            #pragma unroll
            for (int j = 0; j < NT; j++) {
                float v0 = c[i][j][2*h], v1 = c[i][j][2*h+1];
                s += v0 + v1;
                q += v0*v0 + v1*v1;
            }
            s += __shfl_xor_sync(0xffffffffu, s, 1);
            s += __shfl_xor_sync(0xffffffffu, s, 2);
            q += __shfl_xor_sync(0xffffffffu, q, 1);
            q += __shfl_xor_sync(0xffffffffu, q, 2);
            if ((lane & 3) == 0) {
                int row = wm + i*16 + r0 + h*8;
                Rsum[(wid & 3)*64 + row] = s;
                Rsq [(wid & 3)*64 + row] = q;
            }
        }
    }
    __syncthreads();

    float* NFb = NF + (size_t)(by * BM + wm) * Ndim + wn;
    #pragma unroll
    for (int i = 0; i < MT; i++) {
        #pragma unroll
        for (int h = 0; h < 2; h++) {
            int row = wm + i*16 + r0 + h*8;
            float S = Rsum[row] + Rsum[64+row] + Rsum[128+row] + Rsum[192+row];
            float Q = Rsq[row]  + Rsq[64+row]  + Rsq[128+row]  + Rsq[192+row];
            float mu = S * (1.f/RD_);
            float var = Q * (1.f/RD_) - mu*mu;
            float istd = rsqrtf(fmaxf(var, 0.f) + EPS_);
            #pragma unroll
            for (int j = 0; j < NT; j++) {
                float y0 = lrelu_f((c[i][j][2*h]   - mu) * istd);
                float y1 = lrelu_f((c[i][j][2*h+1] - mu) * istd);
                *(float2*)(NFb + (size_t)(i*16 + r0 + h*8) * Ndim + j*8 + c0) =
                    make_float2(y0, y1);
            }
        }
    }
}

// ---------------- mesh CSR build ----------------
__global__ void __launch_bounds__(1024)
k_mesh_csr(const int* __restrict__ msrc, const int* __restrict__ mdst,
           const float* __restrict__ mew)
{
    __shared__ int   co[M_], ci[M_], cur[M_];
    __shared__ float mo[M_];
    __shared__ int   wsum[32], woff[32];

    const int b = blockIdx.x, t = threadIdx.x;
    const int lane = t & 31, wid = t >> 5;

    for (int i = b*1024 + t; i < POOL_W; i += B_*1024) g_pool[i] = 0.f;

    co[t] = 0; ci[t] = 0;
    __syncthreads();
    const int* sp = msrc + b*ME_;
    const int* dp = mdst + b*ME_;
    #pragma unroll
    for (int e = t; e < ME_; e += 1024) {
        atomicAdd(&co[sp[e]], 1);
        atomicAdd(&ci[dp[e]], 1);
    }
    __syncthreads();

    float mout = rsqrtf(fmaxf((float)co[t], 1.f));
    mo[t] = mout;
    g_mins[b*M_ + t] = rsqrtf(fmaxf((float)ci[t], 1.f));

    int v = ci[t];
    int incl = v;
    #pragma unroll
    for (int o = 1; o < 32; o <<= 1) {
        int u = __shfl_up_sync(0xffffffffu, incl, o);
        if (lane >= o) incl += u;
    }
    if (lane == 31) wsum[wid] = incl;
    __syncthreads();
    if (wid == 0) {
        int wv = wsum[lane];
        int wi = wv;
        #pragma unroll
        for (int o = 1; o < 32; o <<= 1) {
            int u = __shfl_up_sync(0xffffffffu, wi, o);
            if (lane >= o) wi += u;
        }
        woff[lane] = wi - wv;
    }
    __syncthreads();
    int excl = incl - v + woff[wid];
    g_rowstart[b*M_ + t] = excl;
    cur[t] = excl;
    __syncthreads();

    const float* wp = mew + b*ME_;
    #pragma unroll
    for (int e = t; e < ME_; e += 1024) {
        int s = sp[e], d = dp[e];
        int pos = atomicAdd(&cur[d], 1);
        g_srcs[b*ME_ + pos] = s;
        g_wgt [b*ME_ + pos] = wp[e] * mo[s];
    }
}

// gather aggregation, float2 channels, optional fused GraphNorm+lrelu
// grid (4096, C/256), 128 threads; each thread owns 2 adjacent channels
template<int C, bool NORM>
__global__ void magg_k(const float* __restrict__ H, float* __restrict__ AGG,
                       const float* __restrict__ s1p, const float* __restrict__ s2p,
                       const float* __restrict__ gamma,
                       const float* __restrict__ beta,
                       const float* __restrict__ alpha)
{
    int node = blockIdx.x;
    int b = node >> 10;
    int n = node & (M_-1);
    int c = (blockIdx.y*128 + threadIdx.x) * 2;
    int beg = g_rowstart[node];
    int end = (n==M_-1) ? ME_ : g_rowstart[node+1];
    const int*   sarr = g_srcs + b*ME_;
    const float* warr = g_wgt  + b*ME_;
    const float* Hb = H + (size_t)b*M_*C + c;

    float am0=0.f, am1=0.f, gi0=1.f, gi1=1.f, bt0=0.f, bt1=0.f;
    if constexpr (NORM) {
        float S10 = s1p[b*HM_ + c],   S20 = s2p[b*HM_ + c];
        float S11 = s1p[b*HM_ + c+1], S21 = s2p[b*HM_ + c+1];
        float m0 = S10*(1.f/M_), m1 = S11*(1.f/M_);
        am0 = alpha[c]*m0; am1 = alpha[c+1]*m1;
        float v0 = S20*(1.f/M_) - 2.f*am0*m0 + am0*am0;
        float v1 = S21*(1.f/M_) - 2.f*am1*m1 + am1*am1;
        gi0 = gamma[c]   * rsqrtf(fmaxf(v0,0.f) + EPS_);
        gi1 = gamma[c+1] * rsqrtf(fmaxf(v1,0.f) + EPS_);
        bt0 = beta[c]; bt1 = beta[c+1];
    }

    float a0x=0.f, a0y=0.f, a1x=0.f, a1y=0.f;
    int i = beg;
    for (; i + 1 < end; i += 2) {
        int s0 = sarr[i], s1 = sarr[i+1];
        float w0 = warr[i], w1 = warr[i+1];
        float2 v0 = *(const float2*)(Hb + (size_t)s0*C);
        float2 v1 = *(const float2*)(Hb + (size_t)s1*C);
        if constexpr (NORM) {
            v0.x = lrelu_f(gi0*(v0.x-am0)+bt0); v0.y = lrelu_f(gi1*(v0.y-am1)+bt1);
            v1.x = lrelu_f(gi0*(v1.x-am0)+bt0); v1.y = lrelu_f(gi1*(v1.y-am1)+bt1);
        }
        a0x += v0.x*w0; a0y += v0.y*w0;
        a1x += v1.x*w1; a1y += v1.y*w1;
    }
    for (; i < end; i++) {
        float w0 = warr[i];
        float2 v0 = *(const float2*)(Hb + (size_t)sarr[i]*C);
        if constexpr (NORM) {
            v0.x = lrelu_f(gi0*(v0.x-am0)+bt0); v0.y = lrelu_f(gi1*(v0.y-am1)+bt1);
        }
        a0x += v0.x*w0; a0y += v0.y*w0;
    }
    float mins = g_mins[node];
    *(float2*)(AGG + (size_t)node*C + c) =
        make_float2((a0x+a1x)*mins, (a0y+a1y)*mins);
}

// normalize + lrelu + column-mean readout (no tensor write)
__global__ void k_readout(const float* __restrict__ Hpre,
                          const float* __restrict__ s1p, const float* __restrict__ s2p,
                          const float* __restrict__ gamma,
                          const float* __restrict__ beta,
                          const float* __restrict__ alpha, int off)
{
    int c = blockIdx.x*128 + threadIdx.x;            // 0..511
    int rbase = blockIdx.y*64;
    int b = rbase >> 10;
    float* block = g_pool + 4*B_*HM_;

    float S1 = s1p[b*HM_ + c];
    float S2 = s2p[b*HM_ + c];
    float mean = S1 * (1.f/M_);
    float am   = alpha[c] * mean;
    float var  = S2*(1.f/M_) - 2.f*am*mean + am*am;
    float gi = gamma[c] * rsqrtf(fmaxf(var, 0.f) + EPS_);
    float bb = beta[c];

    float acc = 0.f;
    const float* Hp = Hpre + (size_t)rbase*HM_ + c;
    #pragma unroll 4
    for (int r = 0; r < 64; r++) {
        float v = Hp[(size_t)r*HM_];
        acc += lrelu_f(gi*(v-am) + bb);
    }
    atomicAdd(&block[b*2*HM_ + off + c], acc);
}

__global__ void final_kernel(const float* __restrict__ Wc, float* __restrict__ out)
{
    int t = threadIdx.x;
    const float* block = g_pool + 4*B_*HM_;
    float acc[OUT_];
    #pragma unroll
    for (int o=0;o<OUT_;o++) acc[o]=0.f;
    for (int i=t;i<B_*2*HM_;i+=256) {
        float v = lrelu_f(block[i] * (1.f/M_));
        #pragma unroll
        for (int o=0;o<OUT_;o++) acc[o] += v*Wc[(size_t)i*OUT_+o];
    }
    __shared__ float red[OUT_][256];
    #pragma unroll
    for (int o=0;o<OUT_;o++) red[o][t]=acc[o];
    __syncthreads();
    for (int s=128;s>0;s>>=1) {
        if (t<s) {
            #pragma unroll
            for (int o=0;o<OUT_;o++) red[o][t]+=red[o][t+s];
        }
        __syncthreads();
    }
    if (t<OUT_) out[t]=red[t][0];
}

// ---------------- launcher -------------------------------------------------
extern "C" void kernel_launch(void* const* d_in, const int* in_sizes, int n_in,
                              void* d_out, int out_size)
{
    (void)in_sizes; (void)n_in; (void)out_size;
    const float* feats = (const float*)d_in[0];
    const int*   psrc  = (const int*)  d_in[1];
    const int*   pdst  = (const int*)  d_in[2];
    const float* pew   = (const float*)d_in[3];
    const int*   msrc  = (const int*)  d_in[4];
    const int*   mdst  = (const int*)  d_in[5];
    const float* mew   = (const float*)d_in[6];
    const float* Wp1   = (const float*)d_in[7];
    const float* Wp2   = (const float*)d_in[8];
    const float* W_emb = (const float*)d_in[9];
    const float* gp1_g = (const float*)d_in[10];
    const float* gp1_b = (const float*)d_in[11];
    const float* gp1_a = (const float*)d_in[12];
    const float* gp2_g = (const float*)d_in[13];
    const float* gp2_b = (const float*)d_in[14];
    const float* gp2_a = (const float*)d_in[15];
    const float* gm1_g = (const float*)d_in[16];
    const float* gm1_b = (const float*)d_in[17];
    const float* gm1_a = (const float*)d_in[18];
    const float* gm2_g = (const float*)d_in[19];
    const float* gm2_b = (const float*)d_in[20];
    const float* gm2_a = (const float*)d_in[21];
    const float* Wm1   = (const float*)d_in[22];
    const float* Wm2   = (const float*)d_in[23];
    const float* Wc    = (const float*)d_in[24];
    float* out = (float*)d_out;

    float *pR,*pNF,*pNFa,*pHM,*pHMa,*pHM2,*pPool;
    cudaGetSymbolAddress((void**)&pR,   g_R);
    cudaGetSymbolAddress((void**)&pNF,  g_NF);
    cudaGetSymbolAddress((void**)&pNFa, g_NFa);
    cudaGetSymbolAddress((void**)&pHM,  g_HM);
    cudaGetSymbolAddress((void**)&pHMa, g_HMa);
    cudaGetSymbolAddress((void**)&pHM2, g_HM2);
    cudaGetSymbolAddress((void**)&pPool, g_pool);
    float* pS1a = pPool;
    float* pS2a = pS1a + B_*HM_;
    float* pS1b = pS2a + B_*HM_;
    float* pS2b = pS1b + B_*HM_;

    const int SM128 = (2*128*36 + 2*32*136) * 4;        // 71680 B
    const int SMEMB = (2*64*36 + 2*32*264) * 4;          // 86016 B
    cudaFuncSetAttribute(gemm_tf32<128,128,true>,
                         cudaFuncAttributeMaxDynamicSharedMemorySize, SM128);
    cudaFuncSetAttribute(gemm_embed_in,
                         cudaFuncAttributeMaxDynamicSharedMemorySize, SMEMB);
    cudaFuncSetAttribute(k_patch_all,
                         cudaFuncAttributeMaxDynamicSharedMemorySize, SMB_PATCH);

    // ---- mesh CSR build + pool zero ----
    k_mesh_csr<<<B_, 1024>>>(msrc, mdst, mew);

    // ---- patch phase: single fused kernel ----
    k_patch_all<<<P_/2, 256, SMB_PATCH>>>(
        feats, psrc, pdst, pew, Wp1, Wp2,
        gp1_g, gp1_b, gp1_a, gp2_g, gp2_b, gp2_a);

    // ---- embed GEMM + fused instance norm ----
    gemm_embed_in<<<P_/64, 256, SMEMB>>>(pR, W_emb, pNF);

    // ---- mesh layer 1 ----
    magg_k<RD_,false><<<dim3(B_*M_, 1), 128>>>(
        pNF, pNFa, nullptr, nullptr, nullptr, nullptr, nullptr);
    gemm_tf32<128,128,true><<<(B_*M_/128)*(HM_/128), 256, SM128>>>(
        pNFa, Wm1, pHM, B_*M_, HM_, RD_, pS1a, pS2a);
    k_readout<<<dim3(HM_/128, B_*M_/64), 128>>>(
        pHM, pS1a, pS2a, gm1_g, gm1_b, gm1_a, 0);

    // ---- mesh layer 2 (norm fused into gather) ----
    magg_k<HM_,true><<<dim3(B_*M_, 2), 128>>>(
        pHM, pHMa, pS1a, pS2a, gm1_g, gm1_b, gm1_a);
    gemm_tf32<128,128,true><<<(B_*M_/128)*(HM_/128), 256, SM128>>>(
        pHMa, Wm2, pHM2, B_*M_, HM_, HM_, pS1b, pS2b);
    k_readout<<<dim3(HM_/128, B_*M_/64), 128>>>(
        pHM2, pS1b, pS2b, gm2_g, gm2_b, gm2_a, HM_);

    // ---- classifier ----
    final_kernel<<<1, 256>>>(Wc, out);
}

// round 11
// speedup vs baseline: 1.0779x; 1.0779x over previous
#include <cuda_runtime.h>
#include <cstdint>

#define P_ 4096
#define PN_ 32
#define PE_ 128
#define B_ 4
#define M_ 1024
#define ME_ 16384
#define IN_ 64
#define HP_ 256
#define HP4_ 64
#define RD_ 256
#define HM_ 512
#define OUT_ 16
#define RTOT_ (IN_+HP_+HP4_)   // 384
#define EPS_ 1e-5f
#define SLOPE_ 0.01f

// ---------------- scratch ----------------
__device__ float g_R  [(size_t)P_*RTOT_];      // readout concat  [4096,384]
__device__ float g_NF [(size_t)P_*RD_];        // node feats      [4096,256]
__device__ float g_NFa[(size_t)B_*M_*RD_];     // mesh-agg node feats
__device__ float g_HM [(size_t)B_*M_*HM_];     // mesh conv1 pre-norm
__device__ float g_HMa[(size_t)B_*M_*HM_];     // mesh-agg (normed) h1
__device__ float g_HM2[(size_t)B_*M_*HM_];     // mesh conv2 pre-norm
__device__ float g_mins[B_*M_], g_mouts[B_*M_];
__device__ int   g_rowstart[B_*M_];
__device__ int   g_srcs[B_*ME_];
__device__ float g_wgt [B_*ME_];
// accumulator pool (zeroed by csr-A CTAs inside k_patch_all):
//  [0,2048) s1 L1  [2048,4096) s2 L1  [4096,6144) s1 L2
//  [6144,8192) s2 L2  [8192,12288) block readout
#define POOL_W 12288
__device__ float g_pool[POOL_W];

// ---------------- tf32 helpers ----------------
__device__ __forceinline__ uint32_t f2tf32(float f) {
    uint32_t u;
    asm("cvt.rna.tf32.f32 %0, %1;" : "=r"(u) : "f"(f));
    return u;
}
__device__ __forceinline__ uint32_t smem_u32(const void* p) {
    return static_cast<uint32_t>(__cvta_generic_to_shared(p));
}
__device__ __forceinline__ void ldsm_x4(uint32_t& r0, uint32_t& r1,
                                        uint32_t& r2, uint32_t& r3, uint32_t addr) {
    asm volatile("ldmatrix.sync.aligned.m8n8.x4.shared.b16 {%0,%1,%2,%3}, [%4];\n"
                 : "=r"(r0), "=r"(r1), "=r"(r2), "=r"(r3) : "r"(addr));
}
__device__ __forceinline__ void mma_tf32(float* c, const uint32_t* a,
                                         uint32_t b0, uint32_t b1) {
    asm volatile(
        "mma.sync.aligned.m16n8k8.row.col.f32.tf32.tf32.f32 "
        "{%0,%1,%2,%3}, {%4,%5,%6,%7}, {%8,%9}, {%0,%1,%2,%3};\n"
        : "+f"(c[0]), "+f"(c[1]), "+f"(c[2]), "+f"(c[3])
        : "r"(a[0]), "r"(a[1]), "r"(a[2]), "r"(a[3]), "r"(b0), "r"(b1));
}
__device__ __forceinline__ float red8(float v) {
    v += __shfl_xor_sync(0xffffffffu, v, 4);
    v += __shfl_xor_sync(0xffffffffu, v, 8);
    v += __shfl_xor_sync(0xffffffffu, v, 16);
    return v;
}
__device__ __forceinline__ float lrelu_f(float x) { return x >= 0.f ? x : SLOPE_*x; }

// ============== fused patch phase + CSR-A: one CTA = 2 patches =============
// blockIdx < 2048: patch pipeline.  blockIdx in [2048,2052): mesh CSR phase A
// (pool zero, degree count, mins/mouts, exclusive scan -> rowstart).
#define SMW_TOTAL 28672
#define SMB_PATCH (SMW_TOTAL*4)

__global__ void __launch_bounds__(256)
k_patch_all(const float* __restrict__ feats, const int* __restrict__ src,
            const int* __restrict__ dst, const float* __restrict__ ew,
            const float* __restrict__ Wp1, const float* __restrict__ Wp2,
            const float* __restrict__ g1g, const float* __restrict__ g1b,
            const float* __restrict__ g1a, const float* __restrict__ g2g,
            const float* __restrict__ g2b, const float* __restrict__ g2a,
            const int* __restrict__ msrc, const int* __restrict__ mdst)
{
    extern __shared__ uint32_t S[];
    const int t    = threadIdx.x;
    const int blk  = blockIdx.x;
    const int lane = t & 31;
    const int wid  = t >> 5;

    // ================= CSR phase A (4 CTAs) =================
    if (blk >= P_/2) {
        const int b = blk - P_/2;
        int* co   = (int*)S;            // [0,1024)
        int* ci   = (int*)S + 1024;     // [1024,2048)
        int* wsum = (int*)S + 2048;     // 8

        for (int i = b*256 + t; i < POOL_W; i += 4*256) g_pool[i] = 0.f;
        #pragma unroll
        for (int k = 0; k < 4; k++) { co[t*4+k] = 0; ci[t*4+k] = 0; }
        __syncthreads();
        const int* sp = msrc + b*ME_;
        const int* dp = mdst + b*ME_;
        for (int e = t; e < ME_; e += 256) {
            atomicAdd(&co[sp[e]], 1);
            atomicAdd(&ci[dp[e]], 1);
        }
        __syncthreads();
        #pragma unroll
        for (int k = 0; k < 4; k++) {
            int n = t*4 + k;
            g_mouts[b*M_+n] = rsqrtf(fmaxf((float)co[n], 1.f));
            g_mins [b*M_+n] = rsqrtf(fmaxf((float)ci[n], 1.f));
        }
        // exclusive scan over 1024 in-degrees; thread owns 4 consecutive
        int loc[4]; int run = 0;
        #pragma unroll
        for (int k = 0; k < 4; k++) { loc[k] = run; run += ci[t*4+k]; }
        int incl = run;
        #pragma unroll
        for (int o = 1; o < 32; o <<= 1) {
            int u = __shfl_up_sync(0xffffffffu, incl, o);
            if (lane >= o) incl += u;
        }
        if (lane == 31) wsum[wid] = incl;
        __syncthreads();
        int wo = 0;
        for (int w = 0; w < wid; w++) wo += wsum[w];
        int base = wo + incl - run;
        #pragma unroll
        for (int k = 0; k < 4; k++)
            g_rowstart[b*M_ + t*4 + k] = base + loc[k];
        return;
    }

    // ================= patch pipeline (2048 CTAs) =================
    float*    WTf  = (float*)S;                  // [64][36] fp32 build
    uint32_t* WT   = S;                          // same, tf32 after cvt
    float*    outs = (float*)(S + 2304);         // 64
    float*    ins  = (float*)(S + 2368);         // 64
    int*      cnt  = (int*)  (S + 2432);         // 128
    uint32_t* Xs   = S + 2560;                   // [64][72] tf32
    uint32_t* A1   = S + 7168;                   // [64][68] tf32
    uint32_t* Bs2  = S + 2560;                   // [128][72] tf32
    uint32_t* B1   = S + 11776;                  // [64][264]
    uint32_t* As2  = S + 11776;                  // [64][260]
    uint32_t* H2s  = S + 11776;                  // [64][72]

    // ---- phase 0: zero WT/cnt, load X (tf32), load Wp1 ----
    #pragma unroll
    for (int i = t; i < 2304; i += 256) WTf[i] = 0.f;
    if (t < 128) cnt[t] = 0;
    {
        const float4* f4 = (const float4*)(feats + (size_t)blk*64*IN_);
        #pragma unroll
        for (int i = 0; i < 4; i++) {
            int lin = t + i*256;
            int lr = lin >> 4, cq = lin & 15;
            float4 v = f4[lin];
            *(uint4*)(Xs + lr*72 + cq*4) =
                make_uint4(f2tf32(v.x), f2tf32(v.y), f2tf32(v.z), f2tf32(v.w));
        }
        const float4* w4 = (const float4*)Wp1;
        #pragma unroll
        for (int i = 0; i < 16; i++) {
            int lin = t + i*256;
            int k = lin >> 6, nq = lin & 63;
            float4 v = w4[lin];
            *(uint4*)(B1 + k*264 + nq*4) =
                make_uint4(f2tf32(v.x), f2tf32(v.y), f2tf32(v.z), f2tf32(v.w));
        }
    }
    __syncthreads();

    // ---- phase 1: dense normalized adjacency (fp32 -> tf32 in place) ----
    {
        int q = t >> 7, e = t & 127;
        int p = blk*2 + q;
        int s = src[p*PE_ + e], d = dst[p*PE_ + e];
        atomicAdd(&WTf[(q*32 + d)*36 + s], ew[p*PE_ + e]);
        atomicAdd(&cnt[q*PN_ + s], 1);
        atomicAdd(&cnt[64 + q*PN_ + d], 1);
    }
    __syncthreads();
    if (t < 64) {
        outs[t] = rsqrtf(fmaxf((float)cnt[t], 1.f));
        ins[t]  = rsqrtf(fmaxf((float)cnt[64 + t], 1.f));
    }
    __syncthreads();
    for (int idx = t; idx < 2304; idx += 256) {
        int row = idx / 36;
        int s = idx - row*36;
        if (s < 32) {
            int q = row >> 5, d = row & 31;
            float v = WTf[idx] * ins[q*32 + d] * outs[q*32 + s];
            WT[idx] = f2tf32(v);
        }
    }
    // r0 readout
    if (t < 128) {
        int q = t >> 6, col = t & 63;
        float s1 = 0.f;
        #pragma unroll
        for (int s = 0; s < PN_; s++)
            s1 += __uint_as_float(Xs[(q*32 + s)*72 + col]);
        g_R[(size_t)(blk*2 + q)*RTOT_ + col] = s1 * (1.f/PN_);
    }
    __syncthreads();

    const int wm  = (wid >> 2) * 32;
    const int q2  = wid >> 2;
    const int arow = wm + (lane & 15);
    const int acol = (lane >> 4) * 4;
    const int bk0  = lane & 3;
    const int r0   = lane >> 2;
    const int c0   = (lane & 3) * 2;

    // ---- phase 2: Xa = Wt @ X via mma -> A1 (tf32) ----
    {
        const int wn2p = (wid & 3) * 16;
        const int bn2  = wn2p + (lane >> 2);
        float cA[2][2][4];
        #pragma unroll
        for (int i = 0; i < 2; i++)
            #pragma unroll
            for (int j = 0; j < 2; j++)
                #pragma unroll
                for (int qq = 0; qq < 4; qq++) cA[i][j][qq] = 0.f;
        #pragma unroll
        for (int ks = 0; ks < 4; ks++) {
            uint32_t a[2][4];
            #pragma unroll
            for (int i = 0; i < 2; i++) {
                uint32_t addr = smem_u32(WT + (arow + i*16)*36 + ks*8 + acol);
                ldsm_x4(a[i][0], a[i][1], a[i][2], a[i][3], addr);
            }
            uint32_t b0[2], b1v[2];
            #pragma unroll
            for (int j = 0; j < 2; j++) {
                b0[j]  = Xs[(q2*32 + ks*8 + bk0)*72 + bn2 + j*8];
                b1v[j] = Xs[(q2*32 + ks*8 + 4 + bk0)*72 + bn2 + j*8];
            }
            #pragma unroll
            for (int i = 0; i < 2; i++)
                #pragma unroll
                for (int j = 0; j < 2; j++)
                    mma_tf32(cA[i][j], a[i], b0[j], b1v[j]);
        }
        #pragma unroll
        for (int i = 0; i < 2; i++)
            #pragma unroll
            for (int j = 0; j < 2; j++) {
                uint32_t* d0 = A1 + (wm + i*16 + r0)*68 + wn2p + j*8 + c0;
                *(uint2*)(d0)        = make_uint2(f2tf32(cA[i][j][0]), f2tf32(cA[i][j][1]));
                *(uint2*)(d0 + 8*68) = make_uint2(f2tf32(cA[i][j][2]), f2tf32(cA[i][j][3]));
            }
    }
    __syncthreads();

    // ---- phase 3: conv1 mma: [64,64] @ [64,256] ----
    const int wn  = (wid & 3) * 64;
    const int bn0 = wn + (lane >> 2);

    float c1[2][8][4];
    #pragma unroll
    for (int i = 0; i < 2; i++)
        #pragma unroll
        for (int j = 0; j < 8; j++)
            #pragma unroll
            for (int q = 0; q < 4; q++) c1[i][j][q] = 0.f;

    #pragma unroll
    for (int ks = 0; ks < 8; ks++) {
        uint32_t a[2][4];
        #pragma unroll
        for (int i = 0; i < 2; i++) {
            uint32_t addr = smem_u32(A1 + (arow + i*16)*68 + ks*8 + acol);
            ldsm_x4(a[i][0], a[i][1], a[i][2], a[i][3], addr);
        }
        uint32_t b0[8], b1v[8];
        #pragma unroll
        for (int j = 0; j < 8; j++) {
            b0[j]  = B1[(ks*8 + bk0)*264 + bn0 + j*8];
            b1v[j] = B1[(ks*8 + 4 + bk0)*264 + bn0 + j*8];
        }
        #pragma unroll
        for (int i = 0; i < 2; i++)
            #pragma unroll
            for (int j = 0; j < 8; j++)
                mma_tf32(c1[i][j], a[i], b0[j], b1v[j]);
    }
    __syncthreads();

    // ---- phase 4: GraphNorm + lrelu + r1; H1 -> As2 (tf32) ----
    {
        const int pat = blk*2 + q2;
        const float inv32 = 1.f / 32.f;
        #pragma unroll
        for (int j = 0; j < 8; j++) {
            int ca = wn + j*8 + c0;
            float va0=c1[0][j][0], va1=c1[0][j][2], va2=c1[1][j][0], va3=c1[1][j][2];
            float vb0=c1[0][j][1], vb1=c1[0][j][3], vb2=c1[1][j][1], vb3=c1[1][j][3];
            float ma = red8(va0+va1+va2+va3) * inv32;
            float mb = red8(vb0+vb1+vb2+vb3) * inv32;
            float ama = __ldg(&g1a[ca])   * ma;
            float amb = __ldg(&g1a[ca+1]) * mb;
            float da0=va0-ama, da1=va1-ama, da2=va2-ama, da3=va3-ama;
            float db0=vb0-amb, db1=vb1-amb, db2=vb2-amb, db3=vb3-amb;
            float qa = red8(da0*da0+da1*da1+da2*da2+da3*da3);
            float qb = red8(db0*db0+db1*db1+db2*db2+db3*db3);
            float ia = rsqrtf(qa*inv32 + EPS_);
            float ib = rsqrtf(qb*inv32 + EPS_);
            float ga = __ldg(&g1g[ca]),   ba = __ldg(&g1b[ca]);
            float gb = __ldg(&g1g[ca+1]), bb = __ldg(&g1b[ca+1]);
            float ha0=lrelu_f(ga*da0*ia+ba), ha1=lrelu_f(ga*da1*ia+ba);
            float ha2=lrelu_f(ga*da2*ia+ba), ha3=lrelu_f(ga*da3*ia+ba);
            float hb0=lrelu_f(gb*db0*ib+bb), hb1=lrelu_f(gb*db1*ib+bb);
            float hb2=lrelu_f(gb*db2*ib+bb), hb3=lrelu_f(gb*db3*ib+bb);
            uint32_t* dst0 = As2 + (wm + r0)*260 + wn + j*8 + c0;
            *(uint2*)(dst0)          = make_uint2(f2tf32(ha0), f2tf32(hb0));
            *(uint2*)(dst0 + 8*260)  = make_uint2(f2tf32(ha1), f2tf32(hb1));
            *(uint2*)(dst0 + 16*260) = make_uint2(f2tf32(ha2), f2tf32(hb2));
            *(uint2*)(dst0 + 24*260) = make_uint2(f2tf32(ha3), f2tf32(hb3));
            float ra = red8(ha0+ha1+ha2+ha3) * inv32;
            float rb = red8(hb0+hb1+hb2+hb3) * inv32;
            if (r0 == 0) {
                g_R[(size_t)pat*RTOT_ + IN_ + ca]     = ra;
                g_R[(size_t)pat*RTOT_ + IN_ + ca + 1] = rb;
            }
        }
    }
    __syncthreads();

    // ---- phase 5: conv2 mma: [64,256] @ [256,64], K in 2 chunks ----
    const int wn2  = (wid & 3) * 16;
    const int bn02 = wn2 + (lane >> 2);
    float c2[2][2][4];
    #pragma unroll
    for (int i = 0; i < 2; i++)
        #pragma unroll
        for (int j = 0; j < 2; j++)
            #pragma unroll
            for (int q = 0; q < 4; q++) c2[i][j][q] = 0.f;

    #pragma unroll
    for (int ch = 0; ch < 2; ch++) {
        const float4* w4 = (const float4*)(Wp2 + (size_t)ch*128*HP4_);
        #pragma unroll
        for (int i = 0; i < 8; i++) {
            int lin = t + i*256;
            int k = lin >> 4, nq = lin & 15;
            float4 v = w4[lin];
            *(uint4*)(Bs2 + k*72 + nq*4) =
                make_uint4(f2tf32(v.x), f2tf32(v.y), f2tf32(v.z), f2tf32(v.w));
        }
        __syncthreads();
        #pragma unroll
        for (int ks = 0; ks < 16; ks++) {
            uint32_t a[2][4];
            #pragma unroll
            for (int i = 0; i < 2; i++) {
                uint32_t addr = smem_u32(As2 + (arow + i*16)*260 + ch*128 + ks*8 + acol);
                ldsm_x4(a[i][0], a[i][1], a[i][2], a[i][3], addr);
            }
            uint32_t b0[2], b1v[2];
            #pragma unroll
            for (int j = 0; j < 2; j++) {
                b0[j]  = Bs2[(ks*8 + bk0)*72 + bn02 + j*8];
                b1v[j] = Bs2[(ks*8 + 4 + bk0)*72 + bn02 + j*8];
            }
            #pragma unroll
            for (int i = 0; i < 2; i++)
                #pragma unroll
                for (int j = 0; j < 2; j++)
                    mma_tf32(c2[i][j], a[i], b0[j], b1v[j]);
        }
        __syncthreads();
    }

    // ---- phase 6: H2 -> smem (tf32, pitch 72) ----
    #pragma unroll
    for (int i = 0; i < 2; i++)
        #pragma unroll
        for (int j = 0; j < 2; j++) {
            uint32_t* d0 = H2s + (wm + i*16 + r0)*72 + wn2 + j*8 + c0;
            *(uint2*)(d0)        = make_uint2(f2tf32(c2[i][j][0]), f2tf32(c2[i][j][1]));
            *(uint2*)(d0 + 8*72) = make_uint2(f2tf32(c2[i][j][2]), f2tf32(c2[i][j][3]));
        }
    __syncthreads();

    // ---- phase 7: agg via mma (Wt @ H2) + GraphNorm + lrelu + r2 ----
    {
        const int wn7 = (wid & 3) * 16;
        const int bn7 = wn7 + (lane >> 2);
        float c7[2][2][4];
        #pragma unroll
        for (int i = 0; i < 2; i++)
            #pragma unroll
            for (int j = 0; j < 2; j++)
                #pragma unroll
                for (int qq = 0; qq < 4; qq++) c7[i][j][qq] = 0.f;
        #pragma unroll
        for (int ks = 0; ks < 4; ks++) {
            uint32_t a[2][4];
            #pragma unroll
            for (int i = 0; i < 2; i++) {
                uint32_t addr = smem_u32(WT + (arow + i*16)*36 + ks*8 + acol);
                ldsm_x4(a[i][0], a[i][1], a[i][2], a[i][3], addr);
            }
            uint32_t b0[2], b1v[2];
            #pragma unroll
            for (int j = 0; j < 2; j++) {
                b0[j]  = H2s[(q2*32 + ks*8 + bk0)*72 + bn7 + j*8];
                b1v[j] = H2s[(q2*32 + ks*8 + 4 + bk0)*72 + bn7 + j*8];
            }
            #pragma unroll
            for (int i = 0; i < 2; i++)
                #pragma unroll
                for (int j = 0; j < 2; j++)
                    mma_tf32(c7[i][j], a[i], b0[j], b1v[j]);
        }
        const int pat = blk*2 + q2;
        const float inv32 = 1.f / 32.f;
        #pragma unroll
        for (int j = 0; j < 2; j++) {
            int ca = wn7 + j*8 + c0;
            float va0=c7[0][j][0], va1=c7[0][j][2], va2=c7[1][j][0], va3=c7[1][j][2];
            float vb0=c7[0][j][1], vb1=c7[0][j][3], vb2=c7[1][j][1], vb3=c7[1][j][3];
            float ma = red8(va0+va1+va2+va3) * inv32;
            float mb = red8(vb0+vb1+vb2+vb3) * inv32;
            float ama = __ldg(&g2a[ca])   * ma;
            float amb = __ldg(&g2a[ca+1]) * mb;
            float da0=va0-ama, da1=va1-ama, da2=va2-ama, da3=va3-ama;
            float db0=vb0-amb, db1=vb1-amb, db2=vb2-amb, db3=vb3-amb;
            float qa = red8(da0*da0+da1*da1+da2*da2+da3*da3);
            float qb = red8(db0*db0+db1*db1+db2*db2+db3*db3);
            float ia = rsqrtf(qa*inv32 + EPS_);
            float ib = rsqrtf(qb*inv32 + EPS_);
            float ga = __ldg(&g2g[ca]),   ba = __ldg(&g2b[ca]);
            float gb = __ldg(&g2g[ca+1]), bb = __ldg(&g2b[ca+1]);
            float ra = red8(lrelu_f(ga*da0*ia+ba) + lrelu_f(ga*da1*ia+ba)
                          + lrelu_f(ga*da2*ia+ba) + lrelu_f(ga*da3*ia+ba)) * inv32;
            float rb = red8(lrelu_f(gb*db0*ib+bb) + lrelu_f(gb*db1*ib+bb)
                          + lrelu_f(gb*db2*ib+bb) + lrelu_f(gb*db3*ib+bb)) * inv32;
            if (r0 == 0) {
                g_R[(size_t)pat*RTOT_ + IN_ + HP_ + ca]     = ra;
                g_R[(size_t)pat*RTOT_ + IN_ + HP_ + ca + 1] = rb;
            }
        }
    }
}

// ---------------- tf32 GEMM (mesh); optional column-stats epilogue ---------
template<int BM, int BN, bool STATS>
__global__ void __launch_bounds__(256)
gemm_tf32(const float* __restrict__ A, const float* __restrict__ B,
          float* __restrict__ C, int Mdim, int Ndim, int Kdim,
          float* __restrict__ s1p, float* __restrict__ s2p)
{
    constexpr int BK  = 32;
    constexpr int WM  = 32;
    constexpr int WN  = BN / 2;
    constexpr int MT  = WM / 16;
    constexpr int NT  = WN / 8;
    constexpr int ASR = BK + 4;
    constexpr int BSR = BN + 8;
    constexpr int ASZ = BM * ASR;
    constexpr int BSZ = BK * BSR;
    constexpr int ALD = BM * BK / 4 / 256;
    constexpr int BLD = BK * BN / 4 / 256;

    extern __shared__ uint32_t sm_[];
    uint32_t* As = sm_;
    uint32_t* Bs = sm_ + 2 * ASZ;

    const int tid  = threadIdx.x;
    const int lane = tid & 31;
    const int wid  = tid >> 5;
    const int nblk = Ndim / BN;
    const int bx = blockIdx.x % nblk;
    const int by = blockIdx.x / nblk;
    const float* Ab = A + (size_t)by * BM * Kdim;
    const float* Bb = B + (size_t)bx * BN;

    const int wm = (wid >> 1) * WM;
    const int wn = (wid & 1) * WN;

    float c[MT][NT][4];
    #pragma unroll
    for (int i = 0; i < MT; i++)
        #pragma unroll
        for (int j = 0; j < NT; j++)
            #pragma unroll
            for (int q = 0; q < 4; q++) c[i][j][q] = 0.f;

    float4 pa[ALD], pb[BLD];

    auto ldgA = [&](int k0) {
        #pragma unroll
        for (int i = 0; i < ALD; i++) {
            int lin = tid + i * 256;
            int row = lin >> 3;
            int kq  = lin & 7;
            pa[i] = *(const float4*)(Ab + (size_t)row * Kdim + k0 + kq * 4);
        }
    };
    auto ldgB = [&](int k0) {
        #pragma unroll
        for (int i = 0; i < BLD; i++) {
            int lin = tid + i * 256;
            int kr = lin / (BN / 4);
            int nq = lin % (BN / 4);
            pb[i] = *(const float4*)(Bb + (size_t)(k0 + kr) * Ndim + nq * 4);
        }
    };
    auto stsA = [&](int buf) {
        uint32_t* base = As + buf * ASZ;
        #pragma unroll
        for (int i = 0; i < ALD; i++) {
            int lin = tid + i * 256;
            int row = lin >> 3;
            int kq  = lin & 7;
            *(uint4*)(base + row * ASR + kq * 4) =
                make_uint4(f2tf32(pa[i].x), f2tf32(pa[i].y),
                           f2tf32(pa[i].z), f2tf32(pa[i].w));
        }
    };
    auto stsB = [&](int buf) {
        uint32_t* base = Bs + buf * BSZ;
        #pragma unroll
        for (int i = 0; i < BLD; i++) {
            int lin = tid + i * 256;
            int kr = lin / (BN / 4);
            int nq = lin % (BN / 4);
            *(uint4*)(base + kr * BSR + nq * 4) =
                make_uint4(f2tf32(pb[i].x), f2tf32(pb[i].y),
                           f2tf32(pb[i].z), f2tf32(pb[i].w));
        }
    };

    const int arow = wm + (lane & 15);
    const int acol = (lane >> 4) * 4;
    const int bn0  = wn + (lane >> 2);
    const int bk0  = lane & 3;

    auto compute = [&](int buf) {
        uint32_t* Abs = As + buf * ASZ;
        uint32_t* Bbs = Bs + buf * BSZ;
        #pragma unroll
        for (int ks = 0; ks < 4; ks++) {
            uint32_t a[MT][4];
            #pragma unroll
            for (int i = 0; i < MT; i++) {
                uint32_t addr = smem_u32(Abs + (arow + i * 16) * ASR + ks * 8 + acol);
                ldsm_x4(a[i][0], a[i][1], a[i][2], a[i][3], addr);
            }
            uint32_t b0[NT], b1[NT];
            #pragma unroll
            for (int j = 0; j < NT; j++) {
                b0[j] = Bbs[(ks * 8 + bk0) * BSR + bn0 + j * 8];
                b1[j] = Bbs[(ks * 8 + 4 + bk0) * BSR + bn0 + j * 8];
            }
            #pragma unroll
            for (int i = 0; i < MT; i++)
                #pragma unroll
                for (int j = 0; j < NT; j++)
                    mma_tf32(c[i][j], a[i], b0[j], b1[j]);
        }
    };

    const int NKT = Kdim / BK;
    ldgA(0); ldgB(0);
    stsA(0); stsB(0);
    __syncthreads();
    for (int kt = 0; kt < NKT; kt++) {
        if (kt + 1 < NKT) { ldgA((kt + 1) * BK); ldgB((kt + 1) * BK); }
        compute(kt & 1);
        if (kt + 1 < NKT) { stsA((kt + 1) & 1); stsB((kt + 1) & 1); }
        __syncthreads();
    }

    float* Cb = C + (size_t)(by * BM + wm) * Ndim + (size_t)bx * BN + wn;
    const int r0 = lane >> 2;
    const int c0 = (lane & 3) * 2;
    #pragma unroll
    for (int i = 0; i < MT; i++)
        #pragma unroll
        for (int j = 0; j < NT; j++) {
            *(float2*)(Cb + (size_t)(i * 16 + r0) * Ndim + j * 8 + c0) =
                make_float2(c[i][j][0], c[i][j][1]);
            *(float2*)(Cb + (size_t)(i * 16 + r0 + 8) * Ndim + j * 8 + c0) =
                make_float2(c[i][j][2], c[i][j][3]);
        }

    if constexpr (STATS) {
        const int b = (by * BM) / M_;
        #pragma unroll
        for (int j = 0; j < NT; j++) {
            int gcol = bx * BN + wn + j * 8 + c0;
            float va0=c[0][j][0], va1=c[0][j][2], va2=c[1][j][0], va3=c[1][j][2];
            float vb0=c[0][j][1], vb1=c[0][j][3], vb2=c[1][j][1], vb3=c[1][j][3];
            float sa = red8(va0+va1+va2+va3);
            float sb = red8(vb0+vb1+vb2+vb3);
            float qa = red8(va0*va0+va1*va1+va2*va2+va3*va3);
            float qb = red8(vb0*vb0+vb1*vb1+vb2*vb2+vb3*vb3);
            if (r0 == 0) {
                atomicAdd(&s1p[b*HM_ + gcol],     sa);
                atomicAdd(&s1p[b*HM_ + gcol + 1], sb);
                atomicAdd(&s2p[b*HM_ + gcol],     qa);
                atomicAdd(&s2p[b*HM_ + gcol + 1], qb);
            }
        }
    }
}

// -------- embed GEMM (fused InstanceNorm) + CSR-B (bucketing) --------------
// blockIdx < 64: embed GEMM row-block.  blockIdx in [64,96): CSR bucketing,
// CTA (b, r) owns destination range [r*128,(r+1)*128) of graph b.
__global__ void __launch_bounds__(256)
gemm_embed_in(const float* __restrict__ A, const float* __restrict__ B,
              float* __restrict__ NF,
              const int* __restrict__ msrc, const int* __restrict__ mdst,
              const float* __restrict__ mew)
{
    extern __shared__ uint32_t sm_[];
    const int tid  = threadIdx.x;

    if (blockIdx.x >= 64) {
        const int blk2 = blockIdx.x - 64;
        const int b = blk2 >> 3, r = blk2 & 7;
        int*   scur = (int*)sm_;            // 128 cursors
        float* smo  = (float*)(sm_ + 128);  // 1024 out-degree scales
        if (tid < 128) scur[tid] = g_rowstart[b*M_ + r*128 + tid];
        for (int i = tid; i < M_; i += 256) smo[i] = g_mouts[b*M_ + i];
        __syncthreads();
        const int* sp = msrc + b*ME_;
        const int* dp = mdst + b*ME_;
        const float* wp = mew + b*ME_;
        const int lo = r*128;
        for (int e = tid; e < ME_; e += 256) {
            int d = dp[e] - lo;
            if ((unsigned)d < 128u) {
                int s = sp[e];
                int pos = atomicAdd(&scur[d], 1);
                g_srcs[b*ME_ + pos] = s;
                g_wgt [b*ME_ + pos] = wp[e] * smo[s];
            }
        }
        return;
    }

    constexpr int BM = 64, BN = 256, BK = 32, Kdim = RTOT_, Ndim = RD_;
    constexpr int NT = 8, MT = 2;
    constexpr int ASR = 36, BSR = 264;
    constexpr int ASZ = BM * ASR;
    constexpr int BSZ = BK * BSR;

    uint32_t* As = sm_;
    uint32_t* Bs = sm_ + 2 * ASZ;

    const int lane = tid & 31;
    const int wid  = tid >> 5;
    const int by = blockIdx.x;
    const float* Ab = A + (size_t)by * BM * Kdim;

    const int wm = (wid >> 2) * 32;
    const int wn = (wid & 3) * 64;

    float c[MT][NT][4];
    #pragma unroll
    for (int i = 0; i < MT; i++)
        #pragma unroll
        for (int j = 0; j < NT; j++)
            #pragma unroll
            for (int q = 0; q < 4; q++) c[i][j][q] = 0.f;

    float4 pa[2], pb[8];
    auto ldgA = [&](int k0) {
        #pragma unroll
        for (int i = 0; i < 2; i++) {
            int lin = tid + i * 256;
            int row = lin >> 3, kq = lin & 7;
            pa[i] = *(const float4*)(Ab + (size_t)row * Kdim + k0 + kq * 4);
        }
    };
    auto ldgB = [&](int k0) {
        #pragma unroll
        for (int i = 0; i < 8; i++) {
            int lin = tid + i * 256;
            int kr = lin >> 6, nq = lin & 63;
            pb[i] = *(const float4*)(B + (size_t)(k0 + kr) * Ndim + nq * 4);
        }
    };
    auto stsA = [&](int buf) {
        uint32_t* base = As + buf * ASZ;
        #pragma unroll
        for (int i = 0; i < 2; i++) {
            int lin = tid + i * 256;
            int row = lin >> 3, kq = lin & 7;
            *(uint4*)(base + row * ASR + kq * 4) =
                make_uint4(f2tf32(pa[i].x), f2tf32(pa[i].y),
                           f2tf32(pa[i].z), f2tf32(pa[i].w));
        }
    };
    auto stsB = [&](int buf) {
        uint32_t* base = Bs + buf * BSZ;
        #pragma unroll
        for (int i = 0; i < 8; i++) {
            int lin = tid + i * 256;
            int kr = lin >> 6, nq = lin & 63;
            *(uint4*)(base + kr * BSR + nq * 4) =
                make_uint4(f2tf32(pb[i].x), f2tf32(pb[i].y),
                           f2tf32(pb[i].z), f2tf32(pb[i].w));
        }
    };

    const int arow = wm + (lane & 15);
    const int acol = (lane >> 4) * 4;
    const int bn0  = wn + (lane >> 2);
    const int bk0  = lane & 3;

    auto compute = [&](int buf) {
        uint32_t* Abs = As + buf * ASZ;
        uint32_t* Bbs = Bs + buf * BSZ;
        #pragma unroll
        for (int ks = 0; ks < 4; ks++) {
            uint32_t a[MT][4];
            #pragma unroll
            for (int i = 0; i < MT; i++) {
                uint32_t addr = smem_u32(Abs + (arow + i * 16) * ASR + ks * 8 + acol);
                ldsm_x4(a[i][0], a[i][1], a[i][2], a[i][3], addr);
            }
            uint32_t b0[NT], b1[NT];
            #pragma unroll
            for (int j = 0; j < NT; j++) {
                b0[j] = Bbs[(ks * 8 + bk0) * BSR + bn0 + j * 8];
                b1[j] = Bbs[(ks * 8 + 4 + bk0) * BSR + bn0 + j * 8];
            }
            #pragma unroll
            for (int i = 0; i < MT; i++)
                #pragma unroll
                for (int j = 0; j < NT; j++)
                    mma_tf32(c[i][j], a[i], b0[j], b1[j]);
        }
    };

    const int NKT = Kdim / BK;
    ldgA(0); ldgB(0);
    stsA(0); stsB(0);
    __syncthreads();
    for (int kt = 0; kt < NKT; kt++) {
        if (kt + 1 < NKT) { ldgA((kt + 1) * BK); ldgB((kt + 1) * BK); }
        compute(kt & 1);
        if (kt + 1 < NKT) { stsA((kt + 1) & 1); stsB((kt + 1) & 1); }
        __syncthreads();
    }
    __syncthreads();

    float* Rsum = (float*)sm_;
    float* Rsq  = (float*)sm_ + 256;
    const int r0 = lane >> 2;
    const int c0 = (lane & 3) * 2;

    #pragma unroll
    for (int i = 0; i < MT; i++) {
        #pragma unroll
        for (int h = 0; h < 2; h++) {
            float s = 0.f, q = 0.f;
            #pragma unroll
            for (int j = 0; j < NT; j++) {
                float v0 = c[i][j][2*h], v1 = c[i][j][2*h+1];
                s += v0 + v1;
                q += v0*v0 + v1*v1;
            }
            s += __shfl_xor_sync(0xffffffffu, s, 1);
            s += __shfl_xor_sync(0xffffffffu, s, 2);
            q += __shfl_xor_sync(0xffffffffu, q, 1);
            q += __shfl_xor_sync(0xffffffffu, q, 2);
            if ((lane & 3) == 0) {
                int row = wm + i*16 + r0 + h*8;
                Rsum[(wid & 3)*64 + row] = s;
                Rsq [(wid & 3)*64 + row] = q;
            }
        }
    }
    __syncthreads();

    float* NFb = NF + (size_t)(by * BM + wm) * Ndim + wn;
    #pragma unroll
    for (int i = 0; i < MT; i++) {
        #pragma unroll
        for (int h = 0; h < 2; h++) {
            int row = wm + i*16 + r0 + h*8;
            float S = Rsum[row] + Rsum[64+row] + Rsum[128+row] + Rsum[192+row];
            float Q = Rsq[row]  + Rsq[64+row]  + Rsq[128+row]  + Rsq[192+row];
            float mu = S * (1.f/RD_);
            float var = Q * (1.f/RD_) - mu*mu;
            float istd = rsqrtf(fmaxf(var, 0.f) + EPS_);
            #pragma unroll
            for (int j = 0; j < NT; j++) {
                float y0 = lrelu_f((c[i][j][2*h]   - mu) * istd);
                float y1 = lrelu_f((c[i][j][2*h+1] - mu) * istd);
                *(float2*)(NFb + (size_t)(i*16 + r0 + h*8) * Ndim + j*8 + c0) =
                    make_float2(y0, y1);
            }
        }
    }
}

// gather aggregation, float2 channels, unroll-4, optional fused GraphNorm
template<int C, bool NORM>
__global__ void magg_k(const float* __restrict__ H, float* __restrict__ AGG,
                       const float* __restrict__ s1p, const float* __restrict__ s2p,
                       const float* __restrict__ gamma,
                       const float* __restrict__ beta,
                       const float* __restrict__ alpha)
{
    int node = blockIdx.x;
    int b = node >> 10;
    int n = node & (M_-1);
    int c = (blockIdx.y*128 + threadIdx.x) * 2;
    int beg = g_rowstart[node];
    int end = (n==M_-1) ? ME_ : g_rowstart[node+1];
    const int*   sarr = g_srcs + b*ME_;
    const float* warr = g_wgt  + b*ME_;
    const float* Hb = H + (size_t)b*M_*C + c;

    float am0=0.f, am1=0.f, gi0=1.f, gi1=1.f, bt0=0.f, bt1=0.f;
    if constexpr (NORM) {
        float S10 = s1p[b*HM_ + c],   S20 = s2p[b*HM_ + c];
        float S11 = s1p[b*HM_ + c+1], S21 = s2p[b*HM_ + c+1];
        float m0 = S10*(1.f/M_), m1 = S11*(1.f/M_);
        am0 = alpha[c]*m0; am1 = alpha[c+1]*m1;
        float v0 = S20*(1.f/M_) - 2.f*am0*m0 + am0*am0;
        float v1 = S21*(1.f/M_) - 2.f*am1*m1 + am1*am1;
        gi0 = gamma[c]   * rsqrtf(fmaxf(v0,0.f) + EPS_);
        gi1 = gamma[c+1] * rsqrtf(fmaxf(v1,0.f) + EPS_);
        bt0 = beta[c]; bt1 = beta[c+1];
    }

    float a0x=0.f, a0y=0.f, a1x=0.f, a1y=0.f;
    float a2x=0.f, a2y=0.f, a3x=0.f, a3y=0.f;
    int i = beg;
    for (; i + 3 < end; i += 4) {
        int s0 = sarr[i],   s1 = sarr[i+1];
        int s2 = sarr[i+2], s3 = sarr[i+3];
        float w0 = warr[i],   w1 = warr[i+1];
        float w2 = warr[i+2], w3 = warr[i+3];
        float2 v0 = *(const float2*)(Hb + (size_t)s0*C);
        float2 v1 = *(const float2*)(Hb + (size_t)s1*C);
        float2 v2 = *(const float2*)(Hb + (size_t)s2*C);
        float2 v3 = *(const float2*)(Hb + (size_t)s3*C);
        if constexpr (NORM) {
            v0.x = lrelu_f(gi0*(v0.x-am0)+bt0); v0.y = lrelu_f(gi1*(v0.y-am1)+bt1);
            v1.x = lrelu_f(gi0*(v1.x-am0)+bt0); v1.y = lrelu_f(gi1*(v1.y-am1)+bt1);
            v2.x = lrelu_f(gi0*(v2.x-am0)+bt0); v2.y = lrelu_f(gi1*(v2.y-am1)+bt1);
            v3.x = lrelu_f(gi0*(v3.x-am0)+bt0); v3.y = lrelu_f(gi1*(v3.y-am1)+bt1);
        }
        a0x += v0.x*w0; a0y += v0.y*w0;
        a1x += v1.x*w1; a1y += v1.y*w1;
        a2x += v2.x*w2; a2y += v2.y*w2;
        a3x += v3.x*w3; a3y += v3.y*w3;
    }
    for (; i < end; i++) {
        float w0 = warr[i];
        float2 v0 = *(const float2*)(Hb + (size_t)sarr[i]*C);
        if constexpr (NORM) {
            v0.x = lrelu_f(gi0*(v0.x-am0)+bt0); v0.y = lrelu_f(gi1*(v0.y-am1)+bt1);
        }
        a0x += v0.x*w0; a0y += v0.y*w0;
    }
    float mins = g_mins[node];
    *(float2*)(AGG + (size_t)node*C + c) =
        make_float2(((a0x+a1x)+(a2x+a3x))*mins, ((a0y+a1y)+(a2y+a3y))*mins);
}

// normalize + lrelu + column-mean readout (no tensor write)
__global__ void k_readout(const float* __restrict__ Hpre,
                          const float* __restrict__ s1p, const float* __restrict__ s2p,
                          const float* __restrict__ gamma,
                          const float* __restrict__ beta,
                          const float* __restrict__ alpha, int off)
{
    int c = blockIdx.x*128 + threadIdx.x;            // 0..511
    int rbase = blockIdx.y*64;
    int b = rbase >> 10;
    float* block = g_pool + 4*B_*HM_;

    float S1 = s1p[b*HM_ + c];
    float S2 = s2p[b*HM_ + c];
    float mean = S1 * (1.f/M_);
    float am   = alpha[c] * mean;
    float var  = S2*(1.f/M_) - 2.f*am*mean + am*am;
    float gi = gamma[c] * rsqrtf(fmaxf(var, 0.f) + EPS_);
    float bb = beta[c];

    float acc = 0.f;
    const float* Hp = Hpre + (size_t)rbase*HM_ + c;
    #pragma unroll 4
    for (int r = 0; r < 64; r++) {
        float v = Hp[(size_t)r*HM_];
        acc += lrelu_f(gi*(v-am) + bb);
    }
    atomicAdd(&block[b*2*HM_ + off + c], acc);
}

__global__ void final_kernel(const float* __restrict__ Wc, float* __restrict__ out)
{
    int t = threadIdx.x;
    const float* block = g_pool + 4*B_*HM_;
    float acc[OUT_];
    #pragma unroll
    for (int o=0;o<OUT_;o++) acc[o]=0.f;
    for (int i=t;i<B_*2*HM_;i+=256) {
        float v = lrelu_f(block[i] * (1.f/M_));
        #pragma unroll
        for (int o=0;o<OUT_;o++) acc[o] += v*Wc[(size_t)i*OUT_+o];
    }
    __shared__ float red[OUT_][256];
    #pragma unroll
    for (int o=0;o<OUT_;o++) red[o][t]=acc[o];
    __syncthreads();
    for (int s=128;s>0;s>>=1) {
        if (t<s) {
            #pragma unroll
            for (int o=0;o<OUT_;o++) red[o][t]+=red[o][t+s];
        }
        __syncthreads();
    }
    if (t<OUT_) out[t]=red[t][0];
}

// ---------------- launcher -------------------------------------------------
extern "C" void kernel_launch(void* const* d_in, const int* in_sizes, int n_in,
                              void* d_out, int out_size)
{
    (void)in_sizes; (void)n_in; (void)out_size;
    const float* feats = (const float*)d_in[0];
    const int*   psrc  = (const int*)  d_in[1];
    const int*   pdst  = (const int*)  d_in[2];
    const float* pew   = (const float*)d_in[3];
    const int*   msrc  = (const int*)  d_in[4];
    const int*   mdst  = (const int*)  d_in[5];
    const float* mew   = (const float*)d_in[6];
    const float* Wp1   = (const float*)d_in[7];
    const float* Wp2   = (const float*)d_in[8];
    const float* W_emb = (const float*)d_in[9];
    const float* gp1_g = (const float*)d_in[10];
    const float* gp1_b = (const float*)d_in[11];
    const float* gp1_a = (const float*)d_in[12];
    const float* gp2_g = (const float*)d_in[13];
    const float* gp2_b = (const float*)d_in[14];
    const float* gp2_a = (const float*)d_in[15];
    const float* gm1_g = (const float*)d_in[16];
    const float* gm1_b = (const float*)d_in[17];
    const float* gm1_a = (const float*)d_in[18];
    const float* gm2_g = (const float*)d_in[19];
    const float* gm2_b = (const float*)d_in[20];
    const float* gm2_a = (const float*)d_in[21];
    const float* Wm1   = (const float*)d_in[22];
    const float* Wm2   = (const float*)d_in[23];
    const float* Wc    = (const float*)d_in[24];
    float* out = (float*)d_out;

    float *pR,*pNF,*pNFa,*pHM,*pHMa,*pHM2,*pPool;
    cudaGetSymbolAddress((void**)&pR,   g_R);
    cudaGetSymbolAddress((void**)&pNF,  g_NF);
    cudaGetSymbolAddress((void**)&pNFa, g_NFa);
    cudaGetSymbolAddress((void**)&pHM,  g_HM);
    cudaGetSymbolAddress((void**)&pHMa, g_HMa);
    cudaGetSymbolAddress((void**)&pHM2, g_HM2);
    cudaGetSymbolAddress((void**)&pPool, g_pool);
    float* pS1a = pPool;
    float* pS2a = pS1a + B_*HM_;
    float* pS1b = pS2a + B_*HM_;
    float* pS2b = pS1b + B_*HM_;

    const int SM128 = (2*128*36 + 2*32*136) * 4;        // 71680 B
    const int SMEMB = (2*64*36 + 2*32*264) * 4;          // 86016 B
    cudaFuncSetAttribute(gemm_tf32<128,128,true>,
                         cudaFuncAttributeMaxDynamicSharedMemorySize, SM128);
    cudaFuncSetAttribute(gemm_embed_in,
                         cudaFuncAttributeMaxDynamicSharedMemorySize, SMEMB);
    cudaFuncSetAttribute(k_patch_all,
                         cudaFuncAttributeMaxDynamicSharedMemorySize, SMB_PATCH);

    // ---- patch phase + CSR-A (hidden under patch waves) ----
    k_patch_all<<<P_/2 + B_, 256, SMB_PATCH>>>(
        feats, psrc, pdst, pew, Wp1, Wp2,
        gp1_g, gp1_b, gp1_a, gp2_g, gp2_b, gp2_a, msrc, mdst);

    // ---- embed GEMM + fused instance norm + CSR-B (hidden under embed) ----
    gemm_embed_in<<<64 + B_*8, 256, SMEMB>>>(pR, W_emb, pNF, msrc, mdst, mew);

    // ---- mesh layer 1 ----
    magg_k<RD_,false><<<dim3(B_*M_, 1), 128>>>(
        pNF, pNFa, nullptr, nullptr, nullptr, nullptr, nullptr);
    gemm_tf32<128,128,true><<<(B_*M_/128)*(HM_/128), 256, SM128>>>(
        pNFa, Wm1, pHM, B_*M_, HM_, RD_, pS1a, pS2a);
    k_readout<<<dim3(HM_/128, B_*M_/64), 128>>>(
        pHM, pS1a, pS2a, gm1_g, gm1_b, gm1_a, 0);

    // ---- mesh layer 2 (norm fused into gather) ----
    magg_k<HM_,true><<<dim3(B_*M_, 2), 128>>>(
        pHM, pHMa, pS1a, pS2a, gm1_g, gm1_b, gm1_a);
    gemm_tf32<128,128,true><<<(B_*M_/128)*(HM_/128), 256, SM128>>>(
        pHMa, Wm2, pHM2, B_*M_, HM_, HM_, pS1b, pS2b);
    k_readout<<<dim3(HM_/128, B_*M_/64), 128>>>(
        pHM2, pS1b, pS2b, gm2_g, gm2_b, gm2_a, HM_);

    // ---- classifier ----
    final_kernel<<<1, 256>>>(Wc, out);
}

// round 15
// speedup vs baseline: 1.0968x; 1.0175x over previous
#include <cuda_runtime.h>
#include <cstdint>

#define P_ 4096
#define PN_ 32
#define PE_ 128
#define B_ 4
#define M_ 1024
#define ME_ 16384
#define IN_ 64
#define HP_ 256
#define HP4_ 64
#define RD_ 256
#define HM_ 512
#define OUT_ 16
#define RTOT_ (IN_+HP_+HP4_)   // 384
#define EPS_ 1e-5f
#define SLOPE_ 0.01f

// ---------------- scratch ----------------
__device__ float g_R  [(size_t)P_*RTOT_];      // readout concat  [4096,384]
__device__ float g_NF [(size_t)P_*RD_];        // node feats      [4096,256]
__device__ float g_NFa[(size_t)B_*M_*RD_];     // mesh-agg node feats
__device__ float g_HM [(size_t)B_*M_*HM_];     // mesh conv1 pre-norm
__device__ float g_HMa[(size_t)B_*M_*HM_];     // mesh-agg (normed) h1
__device__ float g_HM2[(size_t)B_*M_*HM_];     // mesh conv2 pre-norm
__device__ float g_mins[B_*M_], g_mouts[B_*M_];
__device__ int   g_rowstart[B_*M_];
__device__ int   g_srcs[B_*ME_];
__device__ float g_wgt [B_*ME_];
// accumulator pool (zeroed by csr-A CTAs inside k_patch_all):
//  [0,2048) s1 L1  [2048,4096) s2 L1  [4096,6144) s1 L2
//  [6144,8192) s2 L2  [8192,12288) block readout
#define POOL_W 12288
__device__ float g_pool[POOL_W];

// ---------------- tf32 helpers ----------------
__device__ __forceinline__ uint32_t f2tf32(float f) {
    uint32_t u;
    asm("cvt.rna.tf32.f32 %0, %1;" : "=r"(u) : "f"(f));
    return u;
}
__device__ __forceinline__ uint32_t smem_u32(const void* p) {
    return static_cast<uint32_t>(__cvta_generic_to_shared(p));
}
__device__ __forceinline__ void ldsm_x4(uint32_t& r0, uint32_t& r1,
                                        uint32_t& r2, uint32_t& r3, uint32_t addr) {
    asm volatile("ldmatrix.sync.aligned.m8n8.x4.shared.b16 {%0,%1,%2,%3}, [%4];\n"
                 : "=r"(r0), "=r"(r1), "=r"(r2), "=r"(r3) : "r"(addr));
}
__device__ __forceinline__ void mma_tf32(float* c, const uint32_t* a,
                                         uint32_t b0, uint32_t b1) {
    asm volatile(
        "mma.sync.aligned.m16n8k8.row.col.f32.tf32.tf32.f32 "
        "{%0,%1,%2,%3}, {%4,%5,%6,%7}, {%8,%9}, {%0,%1,%2,%3};\n"
        : "+f"(c[0]), "+f"(c[1]), "+f"(c[2]), "+f"(c[3])
        : "r"(a[0]), "r"(a[1]), "r"(a[2]), "r"(a[3]), "r"(b0), "r"(b1));
}
__device__ __forceinline__ float red8(float v) {
    v += __shfl_xor_sync(0xffffffffu, v, 4);
    v += __shfl_xor_sync(0xffffffffu, v, 8);
    v += __shfl_xor_sync(0xffffffffu, v, 16);
    return v;
}
__device__ __forceinline__ float lrelu_f(float x) { return x >= 0.f ? x : SLOPE_*x; }

// ============== fused patch phase + CSR-A: one CTA = 2 patches =============
#define SMW_TOTAL 28672
#define SMB_PATCH (SMW_TOTAL*4)

__global__ void __launch_bounds__(256)
k_patch_all(const float* __restrict__ feats, const int* __restrict__ src,
            const int* __restrict__ dst, const float* __restrict__ ew,
            const float* __restrict__ Wp1, const float* __restrict__ Wp2,
            const float* __restrict__ g1g, const float* __restrict__ g1b,
            const float* __restrict__ g1a, const float* __restrict__ g2g,
            const float* __restrict__ g2b, const float* __restrict__ g2a,
            const int* __restrict__ msrc, const int* __restrict__ mdst)
{
    extern __shared__ uint32_t S[];
    const int t    = threadIdx.x;
    const int blk  = blockIdx.x;
    const int lane = t & 31;
    const int wid  = t >> 5;

    // ================= CSR phase A (4 CTAs) =================
    if (blk >= P_/2) {
        const int b = blk - P_/2;
        int* co   = (int*)S;
        int* ci   = (int*)S + 1024;
        int* wsum = (int*)S + 2048;

        for (int i = b*256 + t; i < POOL_W; i += 4*256) g_pool[i] = 0.f;
        #pragma unroll
        for (int k = 0; k < 4; k++) { co[t*4+k] = 0; ci[t*4+k] = 0; }
        __syncthreads();
        const int* sp = msrc + b*ME_;
        const int* dp = mdst + b*ME_;
        for (int e = t; e < ME_; e += 256) {
            atomicAdd(&co[sp[e]], 1);
            atomicAdd(&ci[dp[e]], 1);
        }
        __syncthreads();
        #pragma unroll
        for (int k = 0; k < 4; k++) {
            int n = t*4 + k;
            g_mouts[b*M_+n] = rsqrtf(fmaxf((float)co[n], 1.f));
            g_mins [b*M_+n] = rsqrtf(fmaxf((float)ci[n], 1.f));
        }
        int loc[4]; int run = 0;
        #pragma unroll
        for (int k = 0; k < 4; k++) { loc[k] = run; run += ci[t*4+k]; }
        int incl = run;
        #pragma unroll
        for (int o = 1; o < 32; o <<= 1) {
            int u = __shfl_up_sync(0xffffffffu, incl, o);
            if (lane >= o) incl += u;
        }
        if (lane == 31) wsum[wid] = incl;
        __syncthreads();
        int wo = 0;
        for (int w = 0; w < wid; w++) wo += wsum[w];
        int base = wo + incl - run;
        #pragma unroll
        for (int k = 0; k < 4; k++)
            g_rowstart[b*M_ + t*4 + k] = base + loc[k];
        return;
    }

    // ================= patch pipeline (2048 CTAs) =================
    float*    WTf  = (float*)S;
    uint32_t* WT   = S;
    float*    outs = (float*)(S + 2304);
    float*    ins  = (float*)(S + 2368);
    int*      cnt  = (int*)  (S + 2432);
    uint32_t* Xs   = S + 2560;                   // [64][72] tf32
    uint32_t* A1   = S + 7168;                   // [64][68] tf32
    uint32_t* Bs2  = S + 2560;                   // [128][72] tf32
    uint32_t* B1   = S + 11776;                  // [64][264]
    uint32_t* As2  = S + 11776;                  // [64][260]
    uint32_t* H2s  = S + 11776;                  // [64][72]

    // ---- phase 0 ----
    #pragma unroll
    for (int i = t; i < 2304; i += 256) WTf[i] = 0.f;
    if (t < 128) cnt[t] = 0;
    {
        const float4* f4 = (const float4*)(feats + (size_t)blk*64*IN_);
        #pragma unroll
        for (int i = 0; i < 4; i++) {
            int lin = t + i*256;
            int lr = lin >> 4, cq = lin & 15;
            float4 v = f4[lin];
            *(uint4*)(Xs + lr*72 + cq*4) =
                make_uint4(f2tf32(v.x), f2tf32(v.y), f2tf32(v.z), f2tf32(v.w));
        }
        const float4* w4 = (const float4*)Wp1;
        #pragma unroll
        for (int i = 0; i < 16; i++) {
            int lin = t + i*256;
            int k = lin >> 6, nq = lin & 63;
            float4 v = w4[lin];
            *(uint4*)(B1 + k*264 + nq*4) =
                make_uint4(f2tf32(v.x), f2tf32(v.y), f2tf32(v.z), f2tf32(v.w));
        }
    }
    __syncthreads();

    // ---- phase 1 ----
    {
        int q = t >> 7, e = t & 127;
        int p = blk*2 + q;
        int s = src[p*PE_ + e], d = dst[p*PE_ + e];
        atomicAdd(&WTf[(q*32 + d)*36 + s], ew[p*PE_ + e]);
        atomicAdd(&cnt[q*PN_ + s], 1);
        atomicAdd(&cnt[64 + q*PN_ + d], 1);
    }
    __syncthreads();
    if (t < 64) {
        outs[t] = rsqrtf(fmaxf((float)cnt[t], 1.f));
        ins[t]  = rsqrtf(fmaxf((float)cnt[64 + t], 1.f));
    }
    __syncthreads();
    for (int idx = t; idx < 2304; idx += 256) {
        int row = idx / 36;
        int s = idx - row*36;
        if (s < 32) {
            int q = row >> 5, d = row & 31;
            float v = WTf[idx] * ins[q*32 + d] * outs[q*32 + s];
            WT[idx] = f2tf32(v);
        }
    }
    if (t < 128) {
        int q = t >> 6, col = t & 63;
        float s1 = 0.f;
        #pragma unroll
        for (int s = 0; s < PN_; s++)
            s1 += __uint_as_float(Xs[(q*32 + s)*72 + col]);
        g_R[(size_t)(blk*2 + q)*RTOT_ + col] = s1 * (1.f/PN_);
    }
    __syncthreads();

    const int wm  = (wid >> 2) * 32;
    const int q2  = wid >> 2;
    const int arow = wm + (lane & 15);
    const int acol = (lane >> 4) * 4;
    const int bk0  = lane & 3;
    const int r0   = lane >> 2;
    const int c0   = (lane & 3) * 2;

    // ---- phase 2 ----
    {
        const int wn2p = (wid & 3) * 16;
        const int bn2  = wn2p + (lane >> 2);
        float cA[2][2][4];
        #pragma unroll
        for (int i = 0; i < 2; i++)
            #pragma unroll
            for (int j = 0; j < 2; j++)
                #pragma unroll
                for (int qq = 0; qq < 4; qq++) cA[i][j][qq] = 0.f;
        #pragma unroll
        for (int ks = 0; ks < 4; ks++) {
            uint32_t a[2][4];
            #pragma unroll
            for (int i = 0; i < 2; i++) {
                uint32_t addr = smem_u32(WT + (arow + i*16)*36 + ks*8 + acol);
                ldsm_x4(a[i][0], a[i][1], a[i][2], a[i][3], addr);
            }
            uint32_t b0[2], b1v[2];
            #pragma unroll
            for (int j = 0; j < 2; j++) {
                b0[j]  = Xs[(q2*32 + ks*8 + bk0)*72 + bn2 + j*8];
                b1v[j] = Xs[(q2*32 + ks*8 + 4 + bk0)*72 + bn2 + j*8];
            }
            #pragma unroll
            for (int i = 0; i < 2; i++)
                #pragma unroll
                for (int j = 0; j < 2; j++)
                    mma_tf32(cA[i][j], a[i], b0[j], b1v[j]);
        }
        #pragma unroll
        for (int i = 0; i < 2; i++)
            #pragma unroll
            for (int j = 0; j < 2; j++) {
                uint32_t* d0 = A1 + (wm + i*16 + r0)*68 + wn2p + j*8 + c0;
                *(uint2*)(d0)        = make_uint2(f2tf32(cA[i][j][0]), f2tf32(cA[i][j][1]));
                *(uint2*)(d0 + 8*68) = make_uint2(f2tf32(cA[i][j][2]), f2tf32(cA[i][j][3]));
            }
    }
    __syncthreads();

    // ---- phase 3 ----
    const int wn  = (wid & 3) * 64;
    const int bn0 = wn + (lane >> 2);

    float c1[2][8][4];
    #pragma unroll
    for (int i = 0; i < 2; i++)
        #pragma unroll
        for (int j = 0; j < 8; j++)
            #pragma unroll
            for (int q = 0; q < 4; q++) c1[i][j][q] = 0.f;

    #pragma unroll
    for (int ks = 0; ks < 8; ks++) {
        uint32_t a[2][4];
        #pragma unroll
        for (int i = 0; i < 2; i++) {
            uint32_t addr = smem_u32(A1 + (arow + i*16)*68 + ks*8 + acol);
            ldsm_x4(a[i][0], a[i][1], a[i][2], a[i][3], addr);
        }
        uint32_t b0[8], b1v[8];
        #pragma unroll
        for (int j = 0; j < 8; j++) {
            b0[j]  = B1[(ks*8 + bk0)*264 + bn0 + j*8];
            b1v[j] = B1[(ks*8 + 4 + bk0)*264 + bn0 + j*8];
        }
        #pragma unroll
        for (int i = 0; i < 2; i++)
            #pragma unroll
            for (int j = 0; j < 8; j++)
                mma_tf32(c1[i][j], a[i], b0[j], b1v[j]);
    }
    __syncthreads();

    // ---- phase 4 ----
    {
        const int pat = blk*2 + q2;
        const float inv32 = 1.f / 32.f;
        #pragma unroll
        for (int j = 0; j < 8; j++) {
            int ca = wn + j*8 + c0;
            float va0=c1[0][j][0], va1=c1[0][j][2], va2=c1[1][j][0], va3=c1[1][j][2];
            float vb0=c1[0][j][1], vb1=c1[0][j][3], vb2=c1[1][j][1], vb3=c1[1][j][3];
            float ma = red8(va0+va1+va2+va3) * inv32;
            float mb = red8(vb0+vb1+vb2+vb3) * inv32;
            float ama = __ldg(&g1a[ca])   * ma;
            float amb = __ldg(&g1a[ca+1]) * mb;
            float da0=va0-ama, da1=va1-ama, da2=va2-ama, da3=va3-ama;
            float db0=vb0-amb, db1=vb1-amb, db2=vb2-amb, db3=vb3-amb;
            float qa = red8(da0*da0+da1*da1+da2*da2+da3*da3);
            float qb = red8(db0*db0+db1*db1+db2*db2+db3*db3);
            float ia = rsqrtf(qa*inv32 + EPS_);
            float ib = rsqrtf(qb*inv32 + EPS_);
            float ga = __ldg(&g1g[ca]),   ba = __ldg(&g1b[ca]);
            float gb = __ldg(&g1g[ca+1]), bb = __ldg(&g1b[ca+1]);
            float ha0=lrelu_f(ga*da0*ia+ba), ha1=lrelu_f(ga*da1*ia+ba);
            float ha2=lrelu_f(ga*da2*ia+ba), ha3=lrelu_f(ga*da3*ia+ba);
            float hb0=lrelu_f(gb*db0*ib+bb), hb1=lrelu_f(gb*db1*ib+bb);
            float hb2=lrelu_f(gb*db2*ib+bb), hb3=lrelu_f(gb*db3*ib+bb);
            uint32_t* dst0 = As2 + (wm + r0)*260 + wn + j*8 + c0;
            *(uint2*)(dst0)          = make_uint2(f2tf32(ha0), f2tf32(hb0));
            *(uint2*)(dst0 + 8*260)  = make_uint2(f2tf32(ha1), f2tf32(hb1));
            *(uint2*)(dst0 + 16*260) = make_uint2(f2tf32(ha2), f2tf32(hb2));
            *(uint2*)(dst0 + 24*260) = make_uint2(f2tf32(ha3), f2tf32(hb3));
            float ra = red8(ha0+ha1+ha2+ha3) * inv32;
            float rb = red8(hb0+hb1+hb2+hb3) * inv32;
            if (r0 == 0) {
                g_R[(size_t)pat*RTOT_ + IN_ + ca]     = ra;
                g_R[(size_t)pat*RTOT_ + IN_ + ca + 1] = rb;
            }
        }
    }
    __syncthreads();

    // ---- phase 5 ----
    const int wn2  = (wid & 3) * 16;
    const int bn02 = wn2 + (lane >> 2);
    float c2[2][2][4];
    #pragma unroll
    for (int i = 0; i < 2; i++)
        #pragma unroll
        for (int j = 0; j < 2; j++)
            #pragma unroll
            for (int q = 0; q < 4; q++) c2[i][j][q] = 0.f;

    #pragma unroll
    for (int ch = 0; ch < 2; ch++) {
        const float4* w4 = (const float4*)(Wp2 + (size_t)ch*128*HP4_);
        #pragma unroll
        for (int i = 0; i < 8; i++) {
            int lin = t + i*256;
            int k = lin >> 4, nq = lin & 15;
            float4 v = w4[lin];
            *(uint4*)(Bs2 + k*72 + nq*4) =
                make_uint4(f2tf32(v.x), f2tf32(v.y), f2tf32(v.z), f2tf32(v.w));
        }
        __syncthreads();
        #pragma unroll
        for (int ks = 0; ks < 16; ks++) {
            uint32_t a[2][4];
            #pragma unroll
            for (int i = 0; i < 2; i++) {
                uint32_t addr = smem_u32(As2 + (arow + i*16)*260 + ch*128 + ks*8 + acol);
                ldsm_x4(a[i][0], a[i][1], a[i][2], a[i][3], addr);
            }
            uint32_t b0[2], b1v[2];
            #pragma unroll
            for (int j = 0; j < 2; j++) {
                b0[j]  = Bs2[(ks*8 + bk0)*72 + bn02 + j*8];
                b1v[j] = Bs2[(ks*8 + 4 + bk0)*72 + bn02 + j*8];
            }
            #pragma unroll
            for (int i = 0; i < 2; i++)
                #pragma unroll
                for (int j = 0; j < 2; j++)
                    mma_tf32(c2[i][j], a[i], b0[j], b1v[j]);
        }
        __syncthreads();
    }

    // ---- phase 6 ----
    #pragma unroll
    for (int i = 0; i < 2; i++)
        #pragma unroll
        for (int j = 0; j < 2; j++) {
            uint32_t* d0 = H2s + (wm + i*16 + r0)*72 + wn2 + j*8 + c0;
            *(uint2*)(d0)        = make_uint2(f2tf32(c2[i][j][0]), f2tf32(c2[i][j][1]));
            *(uint2*)(d0 + 8*72) = make_uint2(f2tf32(c2[i][j][2]), f2tf32(c2[i][j][3]));
        }
    __syncthreads();

    // ---- phase 7 ----
    {
        const int wn7 = (wid & 3) * 16;
        const int bn7 = wn7 + (lane >> 2);
        float c7[2][2][4];
        #pragma unroll
        for (int i = 0; i < 2; i++)
            #pragma unroll
            for (int j = 0; j < 2; j++)
                #pragma unroll
                for (int qq = 0; qq < 4; qq++) c7[i][j][qq] = 0.f;
        #pragma unroll
        for (int ks = 0; ks < 4; ks++) {
            uint32_t a[2][4];
            #pragma unroll
            for (int i = 0; i < 2; i++) {
                uint32_t addr = smem_u32(WT + (arow + i*16)*36 + ks*8 + acol);
                ldsm_x4(a[i][0], a[i][1], a[i][2], a[i][3], addr);
            }
            uint32_t b0[2], b1v[2];
            #pragma unroll
            for (int j = 0; j < 2; j++) {
                b0[j]  = H2s[(q2*32 + ks*8 + bk0)*72 + bn7 + j*8];
                b1v[j] = H2s[(q2*32 + ks*8 + 4 + bk0)*72 + bn7 + j*8];
            }
            #pragma unroll
            for (int i = 0; i < 2; i++)
                #pragma unroll
                for (int j = 0; j < 2; j++)
                    mma_tf32(c7[i][j], a[i], b0[j], b1v[j]);
        }
        const int pat = blk*2 + q2;
        const float inv32 = 1.f / 32.f;
        #pragma unroll
        for (int j = 0; j < 2; j++) {
            int ca = wn7 + j*8 + c0;
            float va0=c7[0][j][0], va1=c7[0][j][2], va2=c7[1][j][0], va3=c7[1][j][2];
            float vb0=c7[0][j][1], vb1=c7[0][j][3], vb2=c7[1][j][1], vb3=c7[1][j][3];
            float ma = red8(va0+va1+va2+va3) * inv32;
            float mb = red8(vb0+vb1+vb2+vb3) * inv32;
            float ama = __ldg(&g2a[ca])   * ma;
            float amb = __ldg(&g2a[ca+1]) * mb;
            float da0=va0-ama, da1=va1-ama, da2=va2-ama, da3=va3-ama;
            float db0=vb0-amb, db1=vb1-amb, db2=vb2-amb, db3=vb3-amb;
            float qa = red8(da0*da0+da1*da1+da2*da2+da3*da3);
            float qb = red8(db0*db0+db1*db1+db2*db2+db3*db3);
            float ia = rsqrtf(qa*inv32 + EPS_);
            float ib = rsqrtf(qb*inv32 + EPS_);
            float ga = __ldg(&g2g[ca]),   ba = __ldg(&g2b[ca]);
            float gb = __ldg(&g2g[ca+1]), bb = __ldg(&g2b[ca+1]);
            float ra = red8(lrelu_f(ga*da0*ia+ba) + lrelu_f(ga*da1*ia+ba)
                          + lrelu_f(ga*da2*ia+ba) + lrelu_f(ga*da3*ia+ba)) * inv32;
            float rb = red8(lrelu_f(gb*db0*ib+bb) + lrelu_f(gb*db1*ib+bb)
                          + lrelu_f(gb*db2*ib+bb) + lrelu_f(gb*db3*ib+bb)) * inv32;
            if (r0 == 0) {
                g_R[(size_t)pat*RTOT_ + IN_ + HP_ + ca]     = ra;
                g_R[(size_t)pat*RTOT_ + IN_ + HP_ + ca + 1] = rb;
            }
        }
    }
}

// ---------------- tf32 GEMM (mesh); warp layout (BM/32) x (8/(BM/32)) ------
template<int BM, int BN, bool STATS>
__global__ void __launch_bounds__(256)
gemm_tf32(const float* __restrict__ A, const float* __restrict__ B,
          float* __restrict__ C, int Mdim, int Ndim, int Kdim,
          float* __restrict__ s1p, float* __restrict__ s2p)
{
    constexpr int BK  = 32;
    constexpr int MW  = BM / 32;          // m-warps
    constexpr int NW  = 8 / MW;           // n-warps
    constexpr int WN  = BN / NW;
    constexpr int MT  = 2;                // 32 rows / 16
    constexpr int NT  = WN / 8;
    constexpr int ASR = BK + 4;
    constexpr int BSR = BN + 8;
    constexpr int ASZ = BM * ASR;
    constexpr int BSZ = BK * BSR;
    constexpr int ALD = BM * BK / 4 / 256;
    constexpr int BLD = BK * BN / 4 / 256;

    extern __shared__ uint32_t sm_[];
    uint32_t* As = sm_;
    uint32_t* Bs = sm_ + 2 * ASZ;

    const int tid  = threadIdx.x;
    const int lane = tid & 31;
    const int wid  = tid >> 5;
    const int nblk = Ndim / BN;
    const int bx = blockIdx.x % nblk;
    const int by = blockIdx.x / nblk;
    const float* Ab = A + (size_t)by * BM * Kdim;
    const float* Bb = B + (size_t)bx * BN;

    const int wm = (wid / NW) * 32;
    const int wn = (wid % NW) * WN;

    float c[MT][NT][4];
    #pragma unroll
    for (int i = 0; i < MT; i++)
        #pragma unroll
        for (int j = 0; j < NT; j++)
            #pragma unroll
            for (int q = 0; q < 4; q++) c[i][j][q] = 0.f;

    float4 pa[ALD], pb[BLD];

    auto ldgA = [&](int k0) {
        #pragma unroll
        for (int i = 0; i < ALD; i++) {
            int lin = tid + i * 256;
            int row = lin >> 3;
            int kq  = lin & 7;
            pa[i] = *(const float4*)(Ab + (size_t)row * Kdim + k0 + kq * 4);
        }
    };
    auto ldgB = [&](int k0) {
        #pragma unroll
        for (int i = 0; i < BLD; i++) {
            int lin = tid + i * 256;
            int kr = lin / (BN / 4);
            int nq = lin % (BN / 4);
            pb[i] = *(const float4*)(Bb + (size_t)(k0 + kr) * Ndim + nq * 4);
        }
    };
    auto stsA = [&](int buf) {
        uint32_t* base = As + buf * ASZ;
        #pragma unroll
        for (int i = 0; i < ALD; i++) {
            int lin = tid + i * 256;
            int row = lin >> 3;
            int kq  = lin & 7;
            *(uint4*)(base + row * ASR + kq * 4) =
                make_uint4(f2tf32(pa[i].x), f2tf32(pa[i].y),
                           f2tf32(pa[i].z), f2tf32(pa[i].w));
        }
    };
    auto stsB = [&](int buf) {
        uint32_t* base = Bs + buf * BSZ;
        #pragma unroll
        for (int i = 0; i < BLD; i++) {
            int lin = tid + i * 256;
            int kr = lin / (BN / 4);
            int nq = lin % (BN / 4);
            *(uint4*)(base + kr * BSR + nq * 4) =
                make_uint4(f2tf32(pb[i].x), f2tf32(pb[i].y),
                           f2tf32(pb[i].z), f2tf32(pb[i].w));
        }
    };

    const int arow = wm + (lane & 15);
    const int acol = (lane >> 4) * 4;
    const int bn0  = wn + (lane >> 2);
    const int bk0  = lane & 3;

    auto compute = [&](int buf) {
        uint32_t* Abs = As + buf * ASZ;
        uint32_t* Bbs = Bs + buf * BSZ;
        #pragma unroll
        for (int ks = 0; ks < 4; ks++) {
            uint32_t a[MT][4];
            #pragma unroll
            for (int i = 0; i < MT; i++) {
                uint32_t addr = smem_u32(Abs + (arow + i * 16) * ASR + ks * 8 + acol);
                ldsm_x4(a[i][0], a[i][1], a[i][2], a[i][3], addr);
            }
            uint32_t b0[NT], b1[NT];
            #pragma unroll
            for (int j = 0; j < NT; j++) {
                b0[j] = Bbs[(ks * 8 + bk0) * BSR + bn0 + j * 8];
                b1[j] = Bbs[(ks * 8 + 4 + bk0) * BSR + bn0 + j * 8];
            }
            #pragma unroll
            for (int i = 0; i < MT; i++)
                #pragma unroll
                for (int j = 0; j < NT; j++)
                    mma_tf32(c[i][j], a[i], b0[j], b1[j]);
        }
    };

    const int NKT = Kdim / BK;
    ldgA(0); ldgB(0);
    stsA(0); stsB(0);
    __syncthreads();
    for (int kt = 0; kt < NKT; kt++) {
        if (kt + 1 < NKT) { ldgA((kt + 1) * BK); ldgB((kt + 1) * BK); }
        compute(kt & 1);
        if (kt + 1 < NKT) { stsA((kt + 1) & 1); stsB((kt + 1) & 1); }
        __syncthreads();
    }

    float* Cb = C + (size_t)(by * BM + wm) * Ndim + (size_t)bx * BN + wn;
    const int r0 = lane >> 2;
    const int c0 = (lane & 3) * 2;
    #pragma unroll
    for (int i = 0; i < MT; i++)
        #pragma unroll
        for (int j = 0; j < NT; j++) {
            *(float2*)(Cb + (size_t)(i * 16 + r0) * Ndim + j * 8 + c0) =
                make_float2(c[i][j][0], c[i][j][1]);
            *(float2*)(Cb + (size_t)(i * 16 + r0 + 8) * Ndim + j * 8 + c0) =
                make_float2(c[i][j][2], c[i][j][3]);
        }

    if constexpr (STATS) {
        const int b = (by * BM) / M_;
        #pragma unroll
        for (int j = 0; j < NT; j++) {
            int gcol = bx * BN + wn + j * 8 + c0;
            float va0=c[0][j][0], va1=c[0][j][2], va2=c[1][j][0], va3=c[1][j][2];
            float vb0=c[0][j][1], vb1=c[0][j][3], vb2=c[1][j][1], vb3=c[1][j][3];
            float sa = red8(va0+va1+va2+va3);
            float sb = red8(vb0+vb1+vb2+vb3);
            float qa = red8(va0*va0+va1*va1+va2*va2+va3*va3);
            float qb = red8(vb0*vb0+vb1*vb1+vb2*vb2+vb3*vb3);
            if (r0 == 0) {
                atomicAdd(&s1p[b*HM_ + gcol],     sa);
                atomicAdd(&s1p[b*HM_ + gcol + 1], sb);
                atomicAdd(&s2p[b*HM_ + gcol],     qa);
                atomicAdd(&s2p[b*HM_ + gcol + 1], qb);
            }
        }
    }
}

// -------- embed GEMM (fused InstanceNorm) + CSR-B (bucketing) --------------
__global__ void __launch_bounds__(256)
gemm_embed_in(const float* __restrict__ A, const float* __restrict__ B,
              float* __restrict__ NF,
              const int* __restrict__ msrc, const int* __restrict__ mdst,
              const float* __restrict__ mew)
{
    extern __shared__ uint32_t sm_[];
    const int tid  = threadIdx.x;

    if (blockIdx.x >= 64) {
        const int blk2 = blockIdx.x - 64;
        const int b = blk2 >> 3, r = blk2 & 7;
        int*   scur = (int*)sm_;
        float* smo  = (float*)(sm_ + 128);
        if (tid < 128) scur[tid] = g_rowstart[b*M_ + r*128 + tid];
        for (int i = tid; i < M_; i += 256) smo[i] = g_mouts[b*M_ + i];
        __syncthreads();
        const int* sp = msrc + b*ME_;
        const int* dp = mdst + b*ME_;
        const float* wp = mew + b*ME_;
        const int lo = r*128;
        for (int e = tid; e < ME_; e += 256) {
            int d = dp[e] - lo;
            if ((unsigned)d < 128u) {
                int s = sp[e];
                int pos = atomicAdd(&scur[d], 1);
                g_srcs[b*ME_ + pos] = s;
                g_wgt [b*ME_ + pos] = wp[e] * smo[s];
            }
        }
        return;
    }

    constexpr int BM = 64, BN = 256, BK = 32, Kdim = RTOT_, Ndim = RD_;
    constexpr int NT = 8, MT = 2;
    constexpr int ASR = 36, BSR = 264;
    constexpr int ASZ = BM * ASR;
    constexpr int BSZ = BK * BSR;

    uint32_t* As = sm_;
    uint32_t* Bs = sm_ + 2 * ASZ;

    const int lane = tid & 31;
    const int wid  = tid >> 5;
    const int by = blockIdx.x;
    const float* Ab = A + (size_t)by * BM * Kdim;

    const int wm = (wid >> 2) * 32;
    const int wn = (wid & 3) * 64;

    float c[MT][NT][4];
    #pragma unroll
    for (int i = 0; i < MT; i++)
        #pragma unroll
        for (int j = 0; j < NT; j++)
            #pragma unroll
            for (int q = 0; q < 4; q++) c[i][j][q] = 0.f;

    float4 pa[2], pb[8];
    auto ldgA = [&](int k0) {
        #pragma unroll
        for (int i = 0; i < 2; i++) {
            int lin = tid + i * 256;
            int row = lin >> 3, kq = lin & 7;
            pa[i] = *(const float4*)(Ab + (size_t)row * Kdim + k0 + kq * 4);
        }
    };
    auto ldgB = [&](int k0) {
        #pragma unroll
        for (int i = 0; i < 8; i++) {
            int lin = tid + i * 256;
            int kr = lin >> 6, nq = lin & 63;
            pb[i] = *(const float4*)(B + (size_t)(k0 + kr) * Ndim + nq * 4);
        }
    };
    auto stsA = [&](int buf) {
        uint32_t* base = As + buf * ASZ;
        #pragma unroll
        for (int i = 0; i < 2; i++) {
            int lin = tid + i * 256;
            int row = lin >> 3, kq = lin & 7;
            *(uint4*)(base + row * ASR + kq * 4) =
                make_uint4(f2tf32(pa[i].x), f2tf32(pa[i].y),
                           f2tf32(pa[i].z), f2tf32(pa[i].w));
        }
    };
    auto stsB = [&](int buf) {
        uint32_t* base = Bs + buf * BSZ;
        #pragma unroll
        for (int i = 0; i < 8; i++) {
            int lin = tid + i * 256;
            int kr = lin >> 6, nq = lin & 63;
            *(uint4*)(base + kr * BSR + nq * 4) =
                make_uint4(f2tf32(pb[i].x), f2tf32(pb[i].y),
                           f2tf32(pb[i].z), f2tf32(pb[i].w));
        }
    };

    const int arow = wm + (lane & 15);
    const int acol = (lane >> 4) * 4;
    const int bn0  = wn + (lane >> 2);
    const int bk0  = lane & 3;

    auto compute = [&](int buf) {
        uint32_t* Abs = As + buf * ASZ;
        uint32_t* Bbs = Bs + buf * BSZ;
        #pragma unroll
        for (int ks = 0; ks < 4; ks++) {
            uint32_t a[MT][4];
            #pragma unroll
            for (int i = 0; i < MT; i++) {
                uint32_t addr = smem_u32(Abs + (arow + i * 16) * ASR + ks * 8 + acol);
                ldsm_x4(a[i][0], a[i][1], a[i][2], a[i][3], addr);
            }
            uint32_t b0[NT], b1[NT];
            #pragma unroll
            for (int j = 0; j < NT; j++) {
                b0[j] = Bbs[(ks * 8 + bk0) * BSR + bn0 + j * 8];
                b1[j] = Bbs[(ks * 8 + 4 + bk0) * BSR + bn0 + j * 8];
            }
            #pragma unroll
            for (int i = 0; i < MT; i++)
                #pragma unroll
                for (int j = 0; j < NT; j++)
                    mma_tf32(c[i][j], a[i], b0[j], b1[j]);
        }
    };

    const int NKT = Kdim / BK;
    ldgA(0); ldgB(0);
    stsA(0); stsB(0);
    __syncthreads();
    for (int kt = 0; kt < NKT; kt++) {
        if (kt + 1 < NKT) { ldgA((kt + 1) * BK); ldgB((kt + 1) * BK); }
        compute(kt & 1);
        if (kt + 1 < NKT) { stsA((kt + 1) & 1); stsB((kt + 1) & 1); }
        __syncthreads();
    }
    __syncthreads();

    float* Rsum = (float*)sm_;
    float* Rsq  = (float*)sm_ + 256;
    const int r0 = lane >> 2;
    const int c0 = (lane & 3) * 2;

    #pragma unroll
    for (int i = 0; i < MT; i++) {
        #pragma unroll
        for (int h = 0; h < 2; h++) {
            float s = 0.f, q = 0.f;
            #pragma unroll
            for (int j = 0; j < NT; j++) {
                float v0 = c[i][j][2*h], v1 = c[i][j][2*h+1];
                s += v0 + v1;
                q += v0*v0 + v1*v1;
            }
            s += __shfl_xor_sync(0xffffffffu, s, 1);
            s += __shfl_xor_sync(0xffffffffu, s, 2);
            q += __shfl_xor_sync(0xffffffffu, q, 1);
            q += __shfl_xor_sync(0xffffffffu, q, 2);
            if ((lane & 3) == 0) {
                int row = wm + i*16 + r0 + h*8;
                Rsum[(wid & 3)*64 + row] = s;
                Rsq [(wid & 3)*64 + row] = q;
            }
        }
    }
    __syncthreads();

    float* NFb = NF + (size_t)(by * BM + wm) * Ndim + wn;
    #pragma unroll
    for (int i = 0; i < MT; i++) {
        #pragma unroll
        for (int h = 0; h < 2; h++) {
            int row = wm + i*16 + r0 + h*8;
            float S = Rsum[row] + Rsum[64+row] + Rsum[128+row] + Rsum[192+row];
            float Q = Rsq[row]  + Rsq[64+row]  + Rsq[128+row]  + Rsq[192+row];
            float mu = S * (1.f/RD_);
            float var = Q * (1.f/RD_) - mu*mu;
            float istd = rsqrtf(fmaxf(var, 0.f) + EPS_);
            #pragma unroll
            for (int j = 0; j < NT; j++) {
                float y0 = lrelu_f((c[i][j][2*h]   - mu) * istd);
                float y1 = lrelu_f((c[i][j][2*h+1] - mu) * istd);
                *(float2*)(NFb + (size_t)(i*16 + r0 + h*8) * Ndim + j*8 + c0) =
                    make_float2(y0, y1);
            }
        }
    }
}

// gather aggregation, float2 channels, unroll-4, optional fused GraphNorm
template<int C, bool NORM>
__global__ void magg_k(const float* __restrict__ H, float* __restrict__ AGG,
                       const float* __restrict__ s1p, const float* __restrict__ s2p,
                       const float* __restrict__ gamma,
                       const float* __restrict__ beta,
                       const float* __restrict__ alpha)
{
    int node = blockIdx.x;
    int b = node >> 10;
    int n = node & (M_-1);
    int c = (blockIdx.y*128 + threadIdx.x) * 2;
    int beg = g_rowstart[node];
    int end = (n==M_-1) ? ME_ : g_rowstart[node+1];
    const int*   sarr = g_srcs + b*ME_;
    const float* warr = g_wgt  + b*ME_;
    const float* Hb = H + (size_t)b*M_*C + c;

    float am0=0.f, am1=0.f, gi0=1.f, gi1=1.f, bt0=0.f, bt1=0.f;
    if constexpr (NORM) {
        float S10 = s1p[b*HM_ + c],   S20 = s2p[b*HM_ + c];
        float S11 = s1p[b*HM_ + c+1], S21 = s2p[b*HM_ + c+1];
        float m0 = S10*(1.f/M_), m1 = S11*(1.f/M_);
        am0 = alpha[c]*m0; am1 = alpha[c+1]*m1;
        float v0 = S20*(1.f/M_) - 2.f*am0*m0 + am0*am0;
        float v1 = S21*(1.f/M_) - 2.f*am1*m1 + am1*am1;
        gi0 = gamma[c]   * rsqrtf(fmaxf(v0,0.f) + EPS_);
        gi1 = gamma[c+1] * rsqrtf(fmaxf(v1,0.f) + EPS_);
        bt0 = beta[c]; bt1 = beta[c+1];
    }

    float a0x=0.f, a0y=0.f, a1x=0.f, a1y=0.f;
    float a2x=0.f, a2y=0.f, a3x=0.f, a3y=0.f;
    int i = beg;
    for (; i + 3 < end; i += 4) {
        int s0 = sarr[i],   s1 = sarr[i+1];
        int s2 = sarr[i+2], s3 = sarr[i+3];
        float w0 = warr[i],   w1 = warr[i+1];
        float w2 = warr[i+2], w3 = warr[i+3];
        float2 v0 = *(const float2*)(Hb + (size_t)s0*C);
        float2 v1 = *(const float2*)(Hb + (size_t)s1*C);
        float2 v2 = *(const float2*)(Hb + (size_t)s2*C);
        float2 v3 = *(const float2*)(Hb + (size_t)s3*C);
        if constexpr (NORM) {
            v0.x = lrelu_f(gi0*(v0.x-am0)+bt0); v0.y = lrelu_f(gi1*(v0.y-am1)+bt1);
            v1.x = lrelu_f(gi0*(v1.x-am0)+bt0); v1.y = lrelu_f(gi1*(v1.y-am1)+bt1);
            v2.x = lrelu_f(gi0*(v2.x-am0)+bt0); v2.y = lrelu_f(gi1*(v2.y-am1)+bt1);
            v3.x = lrelu_f(gi0*(v3.x-am0)+bt0); v3.y = lrelu_f(gi1*(v3.y-am1)+bt1);
        }
        a0x += v0.x*w0; a0y += v0.y*w0;
        a1x += v1.x*w1; a1y += v1.y*w1;
        a2x += v2.x*w2; a2y += v2.y*w2;
        a3x += v3.x*w3; a3y += v3.y*w3;
    }
    for (; i < end; i++) {
        float w0 = warr[i];
        float2 v0 = *(const float2*)(Hb + (size_t)sarr[i]*C);
        if constexpr (NORM) {
            v0.x = lrelu_f(gi0*(v0.x-am0)+bt0); v0.y = lrelu_f(gi1*(v0.y-am1)+bt1);
        }
        a0x += v0.x*w0; a0y += v0.y*w0;
    }
    float mins = g_mins[node];
    *(float2*)(AGG + (size_t)node*C + c) =
        make_float2(((a0x+a1x)+(a2x+a3x))*mins, ((a0y+a1y)+(a2y+a3y))*mins);
}

// normalize + lrelu + column-mean readout (no tensor write)
__global__ void k_readout(const float* __restrict__ Hpre,
                          const float* __restrict__ s1p, const float* __restrict__ s2p,
                          const float* __restrict__ gamma,
                          const float* __restrict__ beta,
                          const float* __restrict__ alpha, int off)
{
    int c = blockIdx.x*128 + threadIdx.x;            // 0..511
    int rbase = blockIdx.y*64;
    int b = rbase >> 10;
    float* block = g_pool + 4*B_*HM_;

    float S1 = s1p[b*HM_ + c];
    float S2 = s2p[b*HM_ + c];
    float mean = S1 * (1.f/M_);
    float am   = alpha[c] * mean;
    float var  = S2*(1.f/M_) - 2.f*am*mean + am*am;
    float gi = gamma[c] * rsqrtf(fmaxf(var, 0.f) + EPS_);
    float bb = beta[c];

    float acc = 0.f;
    const float* Hp = Hpre + (size_t)rbase*HM_ + c;
    #pragma unroll 4
    for (int r = 0; r < 64; r++) {
        float v = Hp[(size_t)r*HM_];
        acc += lrelu_f(gi*(v-am) + bb);
    }
    atomicAdd(&block[b*2*HM_ + off + c], acc);
}

__global__ void final_kernel(const float* __restrict__ Wc, float* __restrict__ out)
{
    int t = threadIdx.x;
    const float* block = g_pool + 4*B_*HM_;
    float acc[OUT_];
    #pragma unroll
    for (int o=0;o<OUT_;o++) acc[o]=0.f;
    for (int i=t;i<B_*2*HM_;i+=256) {
        float v = lrelu_f(block[i] * (1.f/M_));
        #pragma unroll
        for (int o=0;o<OUT_;o++) acc[o] += v*Wc[(size_t)i*OUT_+o];
    }
    __shared__ float red[OUT_][256];
    #pragma unroll
    for (int o=0;o<OUT_;o++) red[o][t]=acc[o];
    __syncthreads();
    for (int s=128;s>0;s>>=1) {
        if (t<s) {
            #pragma unroll
            for (int o=0;o<OUT_;o++) red[o][t]+=red[o][t+s];
        }
        __syncthreads();
    }
    if (t<OUT_) out[t]=red[t][0];
}

// ---------------- launcher -------------------------------------------------
extern "C" void kernel_launch(void* const* d_in, const int* in_sizes, int n_in,
                              void* d_out, int out_size)
{
    (void)in_sizes; (void)n_in; (void)out_size;
    const float* feats = (const float*)d_in[0];
    const int*   psrc  = (const int*)  d_in[1];
    const int*   pdst  = (const int*)  d_in[2];
    const float* pew   = (const float*)d_in[3];
    const int*   msrc  = (const int*)  d_in[4];
    const int*   mdst  = (const int*)  d_in[5];
    const float* mew   = (const float*)d_in[6];
    const float* Wp1   = (const float*)d_in[7];
    const float* Wp2   = (const float*)d_in[8];
    const float* W_emb = (const float*)d_in[9];
    const float* gp1_g = (const float*)d_in[10];
    const float* gp1_b = (const float*)d_in[11];
    const float* gp1_a = (const float*)d_in[12];
    const float* gp2_g = (const float*)d_in[13];
    const float* gp2_b = (const float*)d_in[14];
    const float* gp2_a = (const float*)d_in[15];
    const float* gm1_g = (const float*)d_in[16];
    const float* gm1_b = (const float*)d_in[17];
    const float* gm1_a = (const float*)d_in[18];
    const float* gm2_g = (const float*)d_in[19];
    const float* gm2_b = (const float*)d_in[20];
    const float* gm2_a = (const float*)d_in[21];
    const float* Wm1   = (const float*)d_in[22];
    const float* Wm2   = (const float*)d_in[23];
    const float* Wc    = (const float*)d_in[24];
    float* out = (float*)d_out;

    float *pR,*pNF,*pNFa,*pHM,*pHMa,*pHM2,*pPool;
    cudaGetSymbolAddress((void**)&pR,   g_R);
    cudaGetSymbolAddress((void**)&pNF,  g_NF);
    cudaGetSymbolAddress((void**)&pNFa, g_NFa);
    cudaGetSymbolAddress((void**)&pHM,  g_HM);
    cudaGetSymbolAddress((void**)&pHMa, g_HMa);
    cudaGetSymbolAddress((void**)&pHM2, g_HM2);
    cudaGetSymbolAddress((void**)&pPool, g_pool);
    float* pS1a = (float*)pPool;
    float* pS2a = pS1a + B_*HM_;
    float* pS1b = pS2a + B_*HM_;
    float* pS2b = pS1b + B_*HM_;

    const int SMG  = (2*64*36 + 2*32*136) * 4;           // 53248 B (64x128 tile)
    const int SMEMB = (2*64*36 + 2*32*264) * 4;          // 86016 B
    cudaFuncSetAttribute(gemm_tf32<64,128,true>,
                         cudaFuncAttributeMaxDynamicSharedMemorySize, SMG);
    cudaFuncSetAttribute(gemm_embed_in,
                         cudaFuncAttributeMaxDynamicSharedMemorySize, SMEMB);
    cudaFuncSetAttribute(k_patch_all,
                         cudaFuncAttributeMaxDynamicSharedMemorySize, SMB_PATCH);

    // ---- patch phase + CSR-A (hidden under patch waves) ----
    k_patch_all<<<P_/2 + B_, 256, SMB_PATCH>>>(
        feats, psrc, pdst, pew, Wp1, Wp2,
        gp1_g, gp1_b, gp1_a, gp2_g, gp2_b, gp2_a, msrc, mdst);

    // ---- embed GEMM + fused instance norm + CSR-B (hidden under embed) ----
    gemm_embed_in<<<64 + B_*8, 256, SMEMB>>>(pR, W_emb, pNF, msrc, mdst, mew);

    // ---- mesh layer 1 ----
    magg_k<RD_,false><<<dim3(B_*M_, 1), 128>>>(
        pNF, pNFa, nullptr, nullptr, nullptr, nullptr, nullptr);
    gemm_tf32<64,128,true><<<(B_*M_/64)*(HM_/128), 256, SMG>>>(
        pNFa, Wm1, pHM, B_*M_, HM_, RD_, pS1a, pS2a);
    k_readout<<<dim3(HM_/128, B_*M_/64), 128>>>(
        pHM, pS1a, pS2a, gm1_g, gm1_b, gm1_a, 0);

    // ---- mesh layer 2 (norm fused into gather) ----
    magg_k<HM_,true><<<dim3(B_*M_, 2), 128>>>(
        pHM, pHMa, pS1a, pS2a, gm1_g, gm1_b, gm1_a);
    gemm_tf32<64,128,true><<<(B_*M_/64)*(HM_/128), 256, SMG>>>(
        pHMa, Wm2, pHM2, B_*M_, HM_, HM_, pS1b, pS2b);
    k_readout<<<dim3(HM_/128, B_*M_/64), 128>>>(
        pHM2, pS1b, pS2b, gm2_g, gm2_b, gm2_a, HM_);

    // ---- classifier ----
    final_kernel<<<1, 256>>>(Wc, out);
}

// round 16
// speedup vs baseline: 1.1146x; 1.0163x over previous
#include <cuda_runtime.h>
#include <cstdint>

#define P_ 4096
#define PN_ 32
#define PE_ 128
#define B_ 4
#define M_ 1024
#define ME_ 16384
#define IN_ 64
#define HP_ 256
#define HP4_ 64
#define RD_ 256
#define HM_ 512
#define OUT_ 16
#define RTOT_ (IN_+HP_+HP4_)   // 384
#define EPS_ 1e-5f
#define SLOPE_ 0.01f

// ---------------- scratch ----------------
__device__ float g_R  [(size_t)P_*RTOT_];      // readout concat  [4096,384]
__device__ float g_NF [(size_t)P_*RD_];        // node feats      [4096,256]
__device__ float g_NFa[(size_t)B_*M_*RD_];     // mesh-agg node feats
__device__ float g_HM [(size_t)B_*M_*HM_];     // mesh conv1 pre-norm
__device__ float g_HMa[(size_t)B_*M_*HM_];     // mesh-agg (normed) h1
__device__ float g_HM2[(size_t)B_*M_*HM_];     // mesh conv2 pre-norm
__device__ float g_mins[B_*M_], g_mouts[B_*M_];
__device__ int   g_rowstart[B_*M_];
__device__ int   g_srcs[B_*ME_];
__device__ float g_wgt [B_*ME_];
// accumulator pool (zeroed by csr-A CTAs inside k_patch_all):
//  [0,2048) s1 L1  [2048,4096) s2 L1  [4096,6144) s1 L2
//  [6144,8192) s2 L2  [8192,12288) block readout
#define POOL_W 12288
__device__ float g_pool[POOL_W];

// ---------------- tf32 helpers ----------------
__device__ __forceinline__ uint32_t f2tf32(float f) {
    uint32_t u;
    asm("cvt.rna.tf32.f32 %0, %1;" : "=r"(u) : "f"(f));
    return u;
}
__device__ __forceinline__ uint32_t smem_u32(const void* p) {
    return static_cast<uint32_t>(__cvta_generic_to_shared(p));
}
__device__ __forceinline__ void ldsm_x4(uint32_t& r0, uint32_t& r1,
                                        uint32_t& r2, uint32_t& r3, uint32_t addr) {
    asm volatile("ldmatrix.sync.aligned.m8n8.x4.shared.b16 {%0,%1,%2,%3}, [%4];\n"
                 : "=r"(r0), "=r"(r1), "=r"(r2), "=r"(r3) : "r"(addr));
}
__device__ __forceinline__ void mma_tf32(float* c, const uint32_t* a,
                                         uint32_t b0, uint32_t b1) {
    asm volatile(
        "mma.sync.aligned.m16n8k8.row.col.f32.tf32.tf32.f32 "
        "{%0,%1,%2,%3}, {%4,%5,%6,%7}, {%8,%9}, {%0,%1,%2,%3};\n"
        : "+f"(c[0]), "+f"(c[1]), "+f"(c[2]), "+f"(c[3])
        : "r"(a[0]), "r"(a[1]), "r"(a[2]), "r"(a[3]), "r"(b0), "r"(b1));
}
__device__ __forceinline__ float red8(float v) {
    v += __shfl_xor_sync(0xffffffffu, v, 4);
    v += __shfl_xor_sync(0xffffffffu, v, 8);
    v += __shfl_xor_sync(0xffffffffu, v, 16);
    return v;
}
__device__ __forceinline__ float lrelu_f(float x) { return x >= 0.f ? x : SLOPE_*x; }

// ============== fused patch phase + CSR-A: one CTA = 2 patches =============
#define SMW_TOTAL 28672
#define SMB_PATCH (SMW_TOTAL*4)

__global__ void __launch_bounds__(256)
k_patch_all(const float* __restrict__ feats, const int* __restrict__ src,
            const int* __restrict__ dst, const float* __restrict__ ew,
            const float* __restrict__ Wp1, const float* __restrict__ Wp2,
            const float* __restrict__ g1g, const float* __restrict__ g1b,
            const float* __restrict__ g1a, const float* __restrict__ g2g,
            const float* __restrict__ g2b, const float* __restrict__ g2a,
            const int* __restrict__ msrc, const int* __restrict__ mdst)
{
    extern __shared__ uint32_t S[];
    const int t    = threadIdx.x;
    const int blk  = blockIdx.x;
    const int lane = t & 31;
    const int wid  = t >> 5;

    // ================= CSR phase A (4 CTAs) =================
    if (blk >= P_/2) {
        const int b = blk - P_/2;
        int* co   = (int*)S;
        int* ci   = (int*)S + 1024;
        int* wsum = (int*)S + 2048;

        for (int i = b*256 + t; i < POOL_W; i += 4*256) g_pool[i] = 0.f;
        #pragma unroll
        for (int k = 0; k < 4; k++) { co[t*4+k] = 0; ci[t*4+k] = 0; }
        __syncthreads();
        const int* sp = msrc + b*ME_;
        const int* dp = mdst + b*ME_;
        for (int e = t; e < ME_; e += 256) {
            atomicAdd(&co[sp[e]], 1);
            atomicAdd(&ci[dp[e]], 1);
        }
        __syncthreads();
        #pragma unroll
        for (int k = 0; k < 4; k++) {
            int n = t*4 + k;
            g_mouts[b*M_+n] = rsqrtf(fmaxf((float)co[n], 1.f));
            g_mins [b*M_+n] = rsqrtf(fmaxf((float)ci[n], 1.f));
        }
        int loc[4]; int run = 0;
        #pragma unroll
        for (int k = 0; k < 4; k++) { loc[k] = run; run += ci[t*4+k]; }
        int incl = run;
        #pragma unroll
        for (int o = 1; o < 32; o <<= 1) {
            int u = __shfl_up_sync(0xffffffffu, incl, o);
            if (lane >= o) incl += u;
        }
        if (lane == 31) wsum[wid] = incl;
        __syncthreads();
        int wo = 0;
        for (int w = 0; w < wid; w++) wo += wsum[w];
        int base = wo + incl - run;
        #pragma unroll
        for (int k = 0; k < 4; k++)
            g_rowstart[b*M_ + t*4 + k] = base + loc[k];
        return;
    }

    // ================= patch pipeline (2048 CTAs) =================
    float*    WTf  = (float*)S;
    uint32_t* WT   = S;
    float*    outs = (float*)(S + 2304);
    float*    ins  = (float*)(S + 2368);
    int*      cnt  = (int*)  (S + 2432);
    uint32_t* Xs   = S + 2560;                   // [64][72] tf32
    uint32_t* A1   = S + 7168;                   // [64][68] tf32
    uint32_t* Bs2  = S + 2560;                   // [128][72] tf32
    uint32_t* B1   = S + 11776;                  // [64][264]
    uint32_t* As2  = S + 11776;                  // [64][260]
    uint32_t* H2s  = S + 11776;                  // [64][72]

    // ---- phase 0 ----
    #pragma unroll
    for (int i = t; i < 2304; i += 256) WTf[i] = 0.f;
    if (t < 128) cnt[t] = 0;
    {
        const float4* f4 = (const float4*)(feats + (size_t)blk*64*IN_);
        #pragma unroll
        for (int i = 0; i < 4; i++) {
            int lin = t + i*256;
            int lr = lin >> 4, cq = lin & 15;
            float4 v = f4[lin];
            *(uint4*)(Xs + lr*72 + cq*4) =
                make_uint4(f2tf32(v.x), f2tf32(v.y), f2tf32(v.z), f2tf32(v.w));
        }
        const float4* w4 = (const float4*)Wp1;
        #pragma unroll
        for (int i = 0; i < 16; i++) {
            int lin = t + i*256;
            int k = lin >> 6, nq = lin & 63;
            float4 v = w4[lin];
            *(uint4*)(B1 + k*264 + nq*4) =
                make_uint4(f2tf32(v.x), f2tf32(v.y), f2tf32(v.z), f2tf32(v.w));
        }
    }
    __syncthreads();

    // ---- phase 1 ----
    {
        int q = t >> 7, e = t & 127;
        int p = blk*2 + q;
        int s = src[p*PE_ + e], d = dst[p*PE_ + e];
        atomicAdd(&WTf[(q*32 + d)*36 + s], ew[p*PE_ + e]);
        atomicAdd(&cnt[q*PN_ + s], 1);
        atomicAdd(&cnt[64 + q*PN_ + d], 1);
    }
    __syncthreads();
    if (t < 64) {
        outs[t] = rsqrtf(fmaxf((float)cnt[t], 1.f));
        ins[t]  = rsqrtf(fmaxf((float)cnt[64 + t], 1.f));
    }
    __syncthreads();
    for (int idx = t; idx < 2304; idx += 256) {
        int row = idx / 36;
        int s = idx - row*36;
        if (s < 32) {
            int q = row >> 5, d = row & 31;
            float v = WTf[idx] * ins[q*32 + d] * outs[q*32 + s];
            WT[idx] = f2tf32(v);
        }
    }
    if (t < 128) {
        int q = t >> 6, col = t & 63;
        float s1 = 0.f;
        #pragma unroll
        for (int s = 0; s < PN_; s++)
            s1 += __uint_as_float(Xs[(q*32 + s)*72 + col]);
        g_R[(size_t)(blk*2 + q)*RTOT_ + col] = s1 * (1.f/PN_);
    }
    __syncthreads();

    const int wm  = (wid >> 2) * 32;
    const int q2  = wid >> 2;
    const int arow = wm + (lane & 15);
    const int acol = (lane >> 4) * 4;
    const int bk0  = lane & 3;
    const int r0   = lane >> 2;
    const int c0   = (lane & 3) * 2;

    // ---- phase 2 ----
    {
        const int wn2p = (wid & 3) * 16;
        const int bn2  = wn2p + (lane >> 2);
        float cA[2][2][4];
        #pragma unroll
        for (int i = 0; i < 2; i++)
            #pragma unroll
            for (int j = 0; j < 2; j++)
                #pragma unroll
                for (int qq = 0; qq < 4; qq++) cA[i][j][qq] = 0.f;
        #pragma unroll
        for (int ks = 0; ks < 4; ks++) {
            uint32_t a[2][4];
            #pragma unroll
            for (int i = 0; i < 2; i++) {
                uint32_t addr = smem_u32(WT + (arow + i*16)*36 + ks*8 + acol);
                ldsm_x4(a[i][0], a[i][1], a[i][2], a[i][3], addr);
            }
            uint32_t b0[2], b1v[2];
            #pragma unroll
            for (int j = 0; j < 2; j++) {
                b0[j]  = Xs[(q2*32 + ks*8 + bk0)*72 + bn2 + j*8];
                b1v[j] = Xs[(q2*32 + ks*8 + 4 + bk0)*72 + bn2 + j*8];
            }
            #pragma unroll
            for (int i = 0; i < 2; i++)
                #pragma unroll
                for (int j = 0; j < 2; j++)
                    mma_tf32(cA[i][j], a[i], b0[j], b1v[j]);
        }
        #pragma unroll
        for (int i = 0; i < 2; i++)
            #pragma unroll
            for (int j = 0; j < 2; j++) {
                uint32_t* d0 = A1 + (wm + i*16 + r0)*68 + wn2p + j*8 + c0;
                *(uint2*)(d0)        = make_uint2(f2tf32(cA[i][j][0]), f2tf32(cA[i][j][1]));
                *(uint2*)(d0 + 8*68) = make_uint2(f2tf32(cA[i][j][2]), f2tf32(cA[i][j][3]));
            }
    }
    __syncthreads();

    // ---- phase 3 ----
    const int wn  = (wid & 3) * 64;
    const int bn0 = wn + (lane >> 2);

    float c1[2][8][4];
    #pragma unroll
    for (int i = 0; i < 2; i++)
        #pragma unroll
        for (int j = 0; j < 8; j++)
            #pragma unroll
            for (int q = 0; q < 4; q++) c1[i][j][q] = 0.f;

    #pragma unroll
    for (int ks = 0; ks < 8; ks++) {
        uint32_t a[2][4];
        #pragma unroll
        for (int i = 0; i < 2; i++) {
            uint32_t addr = smem_u32(A1 + (arow + i*16)*68 + ks*8 + acol);
            ldsm_x4(a[i][0], a[i][1], a[i][2], a[i][3], addr);
        }
        uint32_t b0[8], b1v[8];
        #pragma unroll
        for (int j = 0; j < 8; j++) {
            b0[j]  = B1[(ks*8 + bk0)*264 + bn0 + j*8];
            b1v[j] = B1[(ks*8 + 4 + bk0)*264 + bn0 + j*8];
        }
        #pragma unroll
        for (int i = 0; i < 2; i++)
            #pragma unroll
            for (int j = 0; j < 8; j++)
                mma_tf32(c1[i][j], a[i], b0[j], b1v[j]);
    }
    __syncthreads();

    // ---- phase 4 ----
    {
        const int pat = blk*2 + q2;
        const float inv32 = 1.f / 32.f;
        #pragma unroll
        for (int j = 0; j < 8; j++) {
            int ca = wn + j*8 + c0;
            float va0=c1[0][j][0], va1=c1[0][j][2], va2=c1[1][j][0], va3=c1[1][j][2];
            float vb0=c1[0][j][1], vb1=c1[0][j][3], vb2=c1[1][j][1], vb3=c1[1][j][3];
            float ma = red8(va0+va1+va2+va3) * inv32;
            float mb = red8(vb0+vb1+vb2+vb3) * inv32;
            float ama = __ldg(&g1a[ca])   * ma;
            float amb = __ldg(&g1a[ca+1]) * mb;
            float da0=va0-ama, da1=va1-ama, da2=va2-ama, da3=va3-ama;
            float db0=vb0-amb, db1=vb1-amb, db2=vb2-amb, db3=vb3-amb;
            float qa = red8(da0*da0+da1*da1+da2*da2+da3*da3);
            float qb = red8(db0*db0+db1*db1+db2*db2+db3*db3);
            float ia = rsqrtf(qa*inv32 + EPS_);
            float ib = rsqrtf(qb*inv32 + EPS_);
            float ga = __ldg(&g1g[ca]),   ba = __ldg(&g1b[ca]);
            float gb = __ldg(&g1g[ca+1]), bb = __ldg(&g1b[ca+1]);
            float ha0=lrelu_f(ga*da0*ia+ba), ha1=lrelu_f(ga*da1*ia+ba);
            float ha2=lrelu_f(ga*da2*ia+ba), ha3=lrelu_f(ga*da3*ia+ba);
            float hb0=lrelu_f(gb*db0*ib+bb), hb1=lrelu_f(gb*db1*ib+bb);
            float hb2=lrelu_f(gb*db2*ib+bb), hb3=lrelu_f(gb*db3*ib+bb);
            uint32_t* dst0 = As2 + (wm + r0)*260 + wn + j*8 + c0;
            *(uint2*)(dst0)          = make_uint2(f2tf32(ha0), f2tf32(hb0));
            *(uint2*)(dst0 + 8*260)  = make_uint2(f2tf32(ha1), f2tf32(hb1));
            *(uint2*)(dst0 + 16*260) = make_uint2(f2tf32(ha2), f2tf32(hb2));
            *(uint2*)(dst0 + 24*260) = make_uint2(f2tf32(ha3), f2tf32(hb3));
            float ra = red8(ha0+ha1+ha2+ha3) * inv32;
            float rb = red8(hb0+hb1+hb2+hb3) * inv32;
            if (r0 == 0) {
                g_R[(size_t)pat*RTOT_ + IN_ + ca]     = ra;
                g_R[(size_t)pat*RTOT_ + IN_ + ca + 1] = rb;
            }
        }
    }
    __syncthreads();

    // ---- phase 5 ----
    const int wn2  = (wid & 3) * 16;
    const int bn02 = wn2 + (lane >> 2);
    float c2[2][2][4];
    #pragma unroll
    for (int i = 0; i < 2; i++)
        #pragma unroll
        for (int j = 0; j < 2; j++)
            #pragma unroll
            for (int q = 0; q < 4; q++) c2[i][j][q] = 0.f;

    #pragma unroll
    for (int ch = 0; ch < 2; ch++) {
        const float4* w4 = (const float4*)(Wp2 + (size_t)ch*128*HP4_);
        #pragma unroll
        for (int i = 0; i < 8; i++) {
            int lin = t + i*256;
            int k = lin >> 4, nq = lin & 15;
            float4 v = w4[lin];
            *(uint4*)(Bs2 + k*72 + nq*4) =
                make_uint4(f2tf32(v.x), f2tf32(v.y), f2tf32(v.z), f2tf32(v.w));
        }
        __syncthreads();
        #pragma unroll
        for (int ks = 0; ks < 16; ks++) {
            uint32_t a[2][4];
            #pragma unroll
            for (int i = 0; i < 2; i++) {
                uint32_t addr = smem_u32(As2 + (arow + i*16)*260 + ch*128 + ks*8 + acol);
                ldsm_x4(a[i][0], a[i][1], a[i][2], a[i][3], addr);
            }
            uint32_t b0[2], b1v[2];
            #pragma unroll
            for (int j = 0; j < 2; j++) {
                b0[j]  = Bs2[(ks*8 + bk0)*72 + bn02 + j*8];
                b1v[j] = Bs2[(ks*8 + 4 + bk0)*72 + bn02 + j*8];
            }
            #pragma unroll
            for (int i = 0; i < 2; i++)
                #pragma unroll
                for (int j = 0; j < 2; j++)
                    mma_tf32(c2[i][j], a[i], b0[j], b1v[j]);
        }
        __syncthreads();
    }

    // ---- phase 6 ----
    #pragma unroll
    for (int i = 0; i < 2; i++)
        #pragma unroll
        for (int j = 0; j < 2; j++) {
            uint32_t* d0 = H2s + (wm + i*16 + r0)*72 + wn2 + j*8 + c0;
            *(uint2*)(d0)        = make_uint2(f2tf32(c2[i][j][0]), f2tf32(c2[i][j][1]));
            *(uint2*)(d0 + 8*72) = make_uint2(f2tf32(c2[i][j][2]), f2tf32(c2[i][j][3]));
        }
    __syncthreads();

    // ---- phase 7 ----
    {
        const int wn7 = (wid & 3) * 16;
        const int bn7 = wn7 + (lane >> 2);
        float c7[2][2][4];
        #pragma unroll
        for (int i = 0; i < 2; i++)
            #pragma unroll
            for (int j = 0; j < 2; j++)
                #pragma unroll
                for (int qq = 0; qq < 4; qq++) c7[i][j][qq] = 0.f;
        #pragma unroll
        for (int ks = 0; ks < 4; ks++) {
            uint32_t a[2][4];
            #pragma unroll
            for (int i = 0; i < 2; i++) {
                uint32_t addr = smem_u32(WT + (arow + i*16)*36 + ks*8 + acol);
                ldsm_x4(a[i][0], a[i][1], a[i][2], a[i][3], addr);
            }
            uint32_t b0[2], b1v[2];
            #pragma unroll
            for (int j = 0; j < 2; j++) {
                b0[j]  = H2s[(q2*32 + ks*8 + bk0)*72 + bn7 + j*8];
                b1v[j] = H2s[(q2*32 + ks*8 + 4 + bk0)*72 + bn7 + j*8];
            }
            #pragma unroll
            for (int i = 0; i < 2; i++)
                #pragma unroll
                for (int j = 0; j < 2; j++)
                    mma_tf32(c7[i][j], a[i], b0[j], b1v[j]);
        }
        const int pat = blk*2 + q2;
        const float inv32 = 1.f / 32.f;
        #pragma unroll
        for (int j = 0; j < 2; j++) {
            int ca = wn7 + j*8 + c0;
            float va0=c7[0][j][0], va1=c7[0][j][2], va2=c7[1][j][0], va3=c7[1][j][2];
            float vb0=c7[0][j][1], vb1=c7[0][j][3], vb2=c7[1][j][1], vb3=c7[1][j][3];
            float ma = red8(va0+va1+va2+va3) * inv32;
            float mb = red8(vb0+vb1+vb2+vb3) * inv32;
            float ama = __ldg(&g2a[ca])   * ma;
            float amb = __ldg(&g2a[ca+1]) * mb;
            float da0=va0-ama, da1=va1-ama, da2=va2-ama, da3=va3-ama;
            float db0=vb0-amb, db1=vb1-amb, db2=vb2-amb, db3=vb3-amb;
            float qa = red8(da0*da0+da1*da1+da2*da2+da3*da3);
            float qb = red8(db0*db0+db1*db1+db2*db2+db3*db3);
            float ia = rsqrtf(qa*inv32 + EPS_);
            float ib = rsqrtf(qb*inv32 + EPS_);
            float ga = __ldg(&g2g[ca]),   ba = __ldg(&g2b[ca]);
            float gb = __ldg(&g2g[ca+1]), bb = __ldg(&g2b[ca+1]);
            float ra = red8(lrelu_f(ga*da0*ia+ba) + lrelu_f(ga*da1*ia+ba)
                          + lrelu_f(ga*da2*ia+ba) + lrelu_f(ga*da3*ia+ba)) * inv32;
            float rb = red8(lrelu_f(gb*db0*ib+bb) + lrelu_f(gb*db1*ib+bb)
                          + lrelu_f(gb*db2*ib+bb) + lrelu_f(gb*db3*ib+bb)) * inv32;
            if (r0 == 0) {
                g_R[(size_t)pat*RTOT_ + IN_ + HP_ + ca]     = ra;
                g_R[(size_t)pat*RTOT_ + IN_ + HP_ + ca + 1] = rb;
            }
        }
    }
}

// ---------------- tf32 GEMM (mesh); warp layout (BM/32) x (8/(BM/32)) ------
template<int BM, int BN, bool STATS>
__global__ void __launch_bounds__(256)
gemm_tf32(const float* __restrict__ A, const float* __restrict__ B,
          float* __restrict__ C, int Mdim, int Ndim, int Kdim,
          float* __restrict__ s1p, float* __restrict__ s2p)
{
    constexpr int BK  = 32;
    constexpr int MW  = BM / 32;          // m-warps
    constexpr int NW  = 8 / MW;           // n-warps
    constexpr int WN  = BN / NW;
    constexpr int MT  = 2;                // 32 rows / 16
    constexpr int NT  = WN / 8;
    constexpr int ASR = BK + 4;
    constexpr int BSR = BN + 8;
    constexpr int ASZ = BM * ASR;
    constexpr int BSZ = BK * BSR;
    constexpr int ALD = BM * BK / 4 / 256;
    constexpr int BLD = BK * BN / 4 / 256;

    extern __shared__ uint32_t sm_[];
    uint32_t* As = sm_;
    uint32_t* Bs = sm_ + 2 * ASZ;

    const int tid  = threadIdx.x;
    const int lane = tid & 31;
    const int wid  = tid >> 5;
    const int nblk = Ndim / BN;
    const int bx = blockIdx.x % nblk;
    const int by = blockIdx.x / nblk;
    const float* Ab = A + (size_t)by * BM * Kdim;
    const float* Bb = B + (size_t)bx * BN;

    const int wm = (wid / NW) * 32;
    const int wn = (wid % NW) * WN;

    float c[MT][NT][4];
    #pragma unroll
    for (int i = 0; i < MT; i++)
        #pragma unroll
        for (int j = 0; j < NT; j++)
            #pragma unroll
            for (int q = 0; q < 4; q++) c[i][j][q] = 0.f;

    float4 pa[ALD], pb[BLD];

    auto ldgA = [&](int k0) {
        #pragma unroll
        for (int i = 0; i < ALD; i++) {
            int lin = tid + i * 256;
            int row = lin >> 3;
            int kq  = lin & 7;
            pa[i] = *(const float4*)(Ab + (size_t)row * Kdim + k0 + kq * 4);
        }
    };
    auto ldgB = [&](int k0) {
        #pragma unroll
        for (int i = 0; i < BLD; i++) {
            int lin = tid + i * 256;
            int kr = lin / (BN / 4);
            int nq = lin % (BN / 4);
            pb[i] = *(const float4*)(Bb + (size_t)(k0 + kr) * Ndim + nq * 4);
        }
    };
    auto stsA = [&](int buf) {
        uint32_t* base = As + buf * ASZ;
        #pragma unroll
        for (int i = 0; i < ALD; i++) {
            int lin = tid + i * 256;
            int row = lin >> 3;
            int kq  = lin & 7;
            *(uint4*)(base + row * ASR + kq * 4) =
                make_uint4(f2tf32(pa[i].x), f2tf32(pa[i].y),
                           f2tf32(pa[i].z), f2tf32(pa[i].w));
        }
    };
    auto stsB = [&](int buf) {
        uint32_t* base = Bs + buf * BSZ;
        #pragma unroll
        for (int i = 0; i < BLD; i++) {
            int lin = tid + i * 256;
            int kr = lin / (BN / 4);
            int nq = lin % (BN / 4);
            *(uint4*)(base + kr * BSR + nq * 4) =
                make_uint4(f2tf32(pb[i].x), f2tf32(pb[i].y),
                           f2tf32(pb[i].z), f2tf32(pb[i].w));
        }
    };

    const int arow = wm + (lane & 15);
    const int acol = (lane >> 4) * 4;
    const int bn0  = wn + (lane >> 2);
    const int bk0  = lane & 3;

    auto compute = [&](int buf) {
        uint32_t* Abs = As + buf * ASZ;
        uint32_t* Bbs = Bs + buf * BSZ;
        #pragma unroll
        for (int ks = 0; ks < 4; ks++) {
            uint32_t a[MT][4];
            #pragma unroll
            for (int i = 0; i < MT; i++) {
                uint32_t addr = smem_u32(Abs + (arow + i * 16) * ASR + ks * 8 + acol);
                ldsm_x4(a[i][0], a[i][1], a[i][2], a[i][3], addr);
            }
            uint32_t b0[NT], b1[NT];
            #pragma unroll
            for (int j = 0; j < NT; j++) {
                b0[j] = Bbs[(ks * 8 + bk0) * BSR + bn0 + j * 8];
                b1[j] = Bbs[(ks * 8 + 4 + bk0) * BSR + bn0 + j * 8];
            }
            #pragma unroll
            for (int i = 0; i < MT; i++)
                #pragma unroll
                for (int j = 0; j < NT; j++)
                    mma_tf32(c[i][j], a[i], b0[j], b1[j]);
        }
    };

    const int NKT = Kdim / BK;
    ldgA(0); ldgB(0);
    stsA(0); stsB(0);
    __syncthreads();
    for (int kt = 0; kt < NKT; kt++) {
        if (kt + 1 < NKT) { ldgA((kt + 1) * BK); ldgB((kt + 1) * BK); }
        compute(kt & 1);
        if (kt + 1 < NKT) { stsA((kt + 1) & 1); stsB((kt + 1) & 1); }
        __syncthreads();
    }

    float* Cb = C + (size_t)(by * BM + wm) * Ndim + (size_t)bx * BN + wn;
    const int r0 = lane >> 2;
    const int c0 = (lane & 3) * 2;
    #pragma unroll
    for (int i = 0; i < MT; i++)
        #pragma unroll
        for (int j = 0; j < NT; j++) {
            *(float2*)(Cb + (size_t)(i * 16 + r0) * Ndim + j * 8 + c0) =
                make_float2(c[i][j][0], c[i][j][1]);
            *(float2*)(Cb + (size_t)(i * 16 + r0 + 8) * Ndim + j * 8 + c0) =
                make_float2(c[i][j][2], c[i][j][3]);
        }

    if constexpr (STATS) {
        const int b = (by * BM) / M_;
        #pragma unroll
        for (int j = 0; j < NT; j++) {
            int gcol = bx * BN + wn + j * 8 + c0;
            float va0=c[0][j][0], va1=c[0][j][2], va2=c[1][j][0], va3=c[1][j][2];
            float vb0=c[0][j][1], vb1=c[0][j][3], vb2=c[1][j][1], vb3=c[1][j][3];
            float sa = red8(va0+va1+va2+va3);
            float sb = red8(vb0+vb1+vb2+vb3);
            float qa = red8(va0*va0+va1*va1+va2*va2+va3*va3);
            float qb = red8(vb0*vb0+vb1*vb1+vb2*vb2+vb3*vb3);
            if (r0 == 0) {
                atomicAdd(&s1p[b*HM_ + gcol],     sa);
                atomicAdd(&s1p[b*HM_ + gcol + 1], sb);
                atomicAdd(&s2p[b*HM_ + gcol],     qa);
                atomicAdd(&s2p[b*HM_ + gcol + 1], qb);
            }
        }
    }
}

// -------- embed GEMM (fused InstanceNorm) + CSR-B (bucketing) --------------
__global__ void __launch_bounds__(256)
gemm_embed_in(const float* __restrict__ A, const float* __restrict__ B,
              float* __restrict__ NF,
              const int* __restrict__ msrc, const int* __restrict__ mdst,
              const float* __restrict__ mew)
{
    extern __shared__ uint32_t sm_[];
    const int tid  = threadIdx.x;

    if (blockIdx.x >= 64) {
        const int blk2 = blockIdx.x - 64;
        const int b = blk2 >> 3, r = blk2 & 7;
        int*   scur = (int*)sm_;
        float* smo  = (float*)(sm_ + 128);
        if (tid < 128) scur[tid] = g_rowstart[b*M_ + r*128 + tid];
        for (int i = tid; i < M_; i += 256) smo[i] = g_mouts[b*M_ + i];
        __syncthreads();
        const int* sp = msrc + b*ME_;
        const int* dp = mdst + b*ME_;
        const float* wp = mew + b*ME_;
        const int lo = r*128;
        for (int e = tid; e < ME_; e += 256) {
            int d = dp[e] - lo;
            if ((unsigned)d < 128u) {
                int s = sp[e];
                int pos = atomicAdd(&scur[d], 1);
                g_srcs[b*ME_ + pos] = s;
                g_wgt [b*ME_ + pos] = wp[e] * smo[s];
            }
        }
        return;
    }

    constexpr int BM = 64, BN = 256, BK = 32, Kdim = RTOT_, Ndim = RD_;
    constexpr int NT = 8, MT = 2;
    constexpr int ASR = 36, BSR = 264;
    constexpr int ASZ = BM * ASR;
    constexpr int BSZ = BK * BSR;

    uint32_t* As = sm_;
    uint32_t* Bs = sm_ + 2 * ASZ;

    const int lane = tid & 31;
    const int wid  = tid >> 5;
    const int by = blockIdx.x;
    const float* Ab = A + (size_t)by * BM * Kdim;

    const int wm = (wid >> 2) * 32;
    const int wn = (wid & 3) * 64;

    float c[MT][NT][4];
    #pragma unroll
    for (int i = 0; i < MT; i++)
        #pragma unroll
        for (int j = 0; j < NT; j++)
            #pragma unroll
            for (int q = 0; q < 4; q++) c[i][j][q] = 0.f;

    float4 pa[2], pb[8];
    auto ldgA = [&](int k0) {
        #pragma unroll
        for (int i = 0; i < 2; i++) {
            int lin = tid + i * 256;
            int row = lin >> 3, kq = lin & 7;
            pa[i] = *(const float4*)(Ab + (size_t)row * Kdim + k0 + kq * 4);
        }
    };
    auto ldgB = [&](int k0) {
        #pragma unroll
        for (int i = 0; i < 8; i++) {
            int lin = tid + i * 256;
            int kr = lin >> 6, nq = lin & 63;
            pb[i] = *(const float4*)(B + (size_t)(k0 + kr) * Ndim + nq * 4);
        }
    };
    auto stsA = [&](int buf) {
        uint32_t* base = As + buf * ASZ;
        #pragma unroll
        for (int i = 0; i < 2; i++) {
            int lin = tid + i * 256;
            int row = lin >> 3, kq = lin & 7;
            *(uint4*)(base + row * ASR + kq * 4) =
                make_uint4(f2tf32(pa[i].x), f2tf32(pa[i].y),
                           f2tf32(pa[i].z), f2tf32(pa[i].w));
        }
    };
    auto stsB = [&](int buf) {
        uint32_t* base = Bs + buf * BSZ;
        #pragma unroll
        for (int i = 0; i < 8; i++) {
            int lin = tid + i * 256;
            int kr = lin >> 6, nq = lin & 63;
            *(uint4*)(base + kr * BSR + nq * 4) =
                make_uint4(f2tf32(pb[i].x), f2tf32(pb[i].y),
                           f2tf32(pb[i].z), f2tf32(pb[i].w));
        }
    };

    const int arow = wm + (lane & 15);
    const int acol = (lane >> 4) * 4;
    const int bn0  = wn + (lane >> 2);
    const int bk0  = lane & 3;

    auto compute = [&](int buf) {
        uint32_t* Abs = As + buf * ASZ;
        uint32_t* Bbs = Bs + buf * BSZ;
        #pragma unroll
        for (int ks = 0; ks < 4; ks++) {
            uint32_t a[MT][4];
            #pragma unroll
            for (int i = 0; i < MT; i++) {
                uint32_t addr = smem_u32(Abs + (arow + i * 16) * ASR + ks * 8 + acol);
                ldsm_x4(a[i][0], a[i][1], a[i][2], a[i][3], addr);
            }
            uint32_t b0[NT], b1[NT];
            #pragma unroll
            for (int j = 0; j < NT; j++) {
                b0[j] = Bbs[(ks * 8 + bk0) * BSR + bn0 + j * 8];
                b1[j] = Bbs[(ks * 8 + 4 + bk0) * BSR + bn0 + j * 8];
            }
            #pragma unroll
            for (int i = 0; i < MT; i++)
                #pragma unroll
                for (int j = 0; j < NT; j++)
                    mma_tf32(c[i][j], a[i], b0[j], b1[j]);
        }
    };

    const int NKT = Kdim / BK;
    ldgA(0); ldgB(0);
    stsA(0); stsB(0);
    __syncthreads();
    for (int kt = 0; kt < NKT; kt++) {
        if (kt + 1 < NKT) { ldgA((kt + 1) * BK); ldgB((kt + 1) * BK); }
        compute(kt & 1);
        if (kt + 1 < NKT) { stsA((kt + 1) & 1); stsB((kt + 1) & 1); }
        __syncthreads();
    }
    __syncthreads();

    float* Rsum = (float*)sm_;
    float* Rsq  = (float*)sm_ + 256;
    const int r0 = lane >> 2;
    const int c0 = (lane & 3) * 2;

    #pragma unroll
    for (int i = 0; i < MT; i++) {
        #pragma unroll
        for (int h = 0; h < 2; h++) {
            float s = 0.f, q = 0.f;
            #pragma unroll
            for (int j = 0; j < NT; j++) {
                float v0 = c[i][j][2*h], v1 = c[i][j][2*h+1];
                s += v0 + v1;
                q += v0*v0 + v1*v1;
            }
            s += __shfl_xor_sync(0xffffffffu, s, 1);
            s += __shfl_xor_sync(0xffffffffu, s, 2);
            q += __shfl_xor_sync(0xffffffffu, q, 1);
            q += __shfl_xor_sync(0xffffffffu, q, 2);
            if ((lane & 3) == 0) {
                int row = wm + i*16 + r0 + h*8;
                Rsum[(wid & 3)*64 + row] = s;
                Rsq [(wid & 3)*64 + row] = q;
            }
        }
    }
    __syncthreads();

    float* NFb = NF + (size_t)(by * BM + wm) * Ndim + wn;
    #pragma unroll
    for (int i = 0; i < MT; i++) {
        #pragma unroll
        for (int h = 0; h < 2; h++) {
            int row = wm + i*16 + r0 + h*8;
            float S = Rsum[row] + Rsum[64+row] + Rsum[128+row] + Rsum[192+row];
            float Q = Rsq[row]  + Rsq[64+row]  + Rsq[128+row]  + Rsq[192+row];
            float mu = S * (1.f/RD_);
            float var = Q * (1.f/RD_) - mu*mu;
            float istd = rsqrtf(fmaxf(var, 0.f) + EPS_);
            #pragma unroll
            for (int j = 0; j < NT; j++) {
                float y0 = lrelu_f((c[i][j][2*h]   - mu) * istd);
                float y1 = lrelu_f((c[i][j][2*h+1] - mu) * istd);
                *(float2*)(NFb + (size_t)(i*16 + r0 + h*8) * Ndim + j*8 + c0) =
                    make_float2(y0, y1);
            }
        }
    }
}

// gather aggregation, float2 channels, unroll-4, optional fused GraphNorm
template<int C, bool NORM>
__device__ __forceinline__
void magg_body(int node, int cy, const float* __restrict__ H,
               float* __restrict__ AGG,
               const float* __restrict__ s1p, const float* __restrict__ s2p,
               const float* __restrict__ gamma, const float* __restrict__ beta,
               const float* __restrict__ alpha)
{
    int b = node >> 10;
    int n = node & (M_-1);
    int c = (cy*128 + threadIdx.x) * 2;
    int beg = g_rowstart[node];
    int end = (n==M_-1) ? ME_ : g_rowstart[node+1];
    const int*   sarr = g_srcs + b*ME_;
    const float* warr = g_wgt  + b*ME_;
    const float* Hb = H + (size_t)b*M_*C + c;

    float am0=0.f, am1=0.f, gi0=1.f, gi1=1.f, bt0=0.f, bt1=0.f;
    if constexpr (NORM) {
        float S10 = s1p[b*HM_ + c],   S20 = s2p[b*HM_ + c];
        float S11 = s1p[b*HM_ + c+1], S21 = s2p[b*HM_ + c+1];
        float m0 = S10*(1.f/M_), m1 = S11*(1.f/M_);
        am0 = alpha[c]*m0; am1 = alpha[c+1]*m1;
        float v0 = S20*(1.f/M_) - 2.f*am0*m0 + am0*am0;
        float v1 = S21*(1.f/M_) - 2.f*am1*m1 + am1*am1;
        gi0 = gamma[c]   * rsqrtf(fmaxf(v0,0.f) + EPS_);
        gi1 = gamma[c+1] * rsqrtf(fmaxf(v1,0.f) + EPS_);
        bt0 = beta[c]; bt1 = beta[c+1];
    }

    float a0x=0.f, a0y=0.f, a1x=0.f, a1y=0.f;
    float a2x=0.f, a2y=0.f, a3x=0.f, a3y=0.f;
    int i = beg;
    for (; i + 3 < end; i += 4) {
        int s0 = sarr[i],   s1 = sarr[i+1];
        int s2 = sarr[i+2], s3 = sarr[i+3];
        float w0 = warr[i],   w1 = warr[i+1];
        float w2 = warr[i+2], w3 = warr[i+3];
        float2 v0 = *(const float2*)(Hb + (size_t)s0*C);
        float2 v1 = *(const float2*)(Hb + (size_t)s1*C);
        float2 v2 = *(const float2*)(Hb + (size_t)s2*C);
        float2 v3 = *(const float2*)(Hb + (size_t)s3*C);
        if constexpr (NORM) {
            v0.x = lrelu_f(gi0*(v0.x-am0)+bt0); v0.y = lrelu_f(gi1*(v0.y-am1)+bt1);
            v1.x = lrelu_f(gi0*(v1.x-am0)+bt0); v1.y = lrelu_f(gi1*(v1.y-am1)+bt1);
            v2.x = lrelu_f(gi0*(v2.x-am0)+bt0); v2.y = lrelu_f(gi1*(v2.y-am1)+bt1);
            v3.x = lrelu_f(gi0*(v3.x-am0)+bt0); v3.y = lrelu_f(gi1*(v3.y-am1)+bt1);
        }
        a0x += v0.x*w0; a0y += v0.y*w0;
        a1x += v1.x*w1; a1y += v1.y*w1;
        a2x += v2.x*w2; a2y += v2.y*w2;
        a3x += v3.x*w3; a3y += v3.y*w3;
    }
    for (; i < end; i++) {
        float w0 = warr[i];
        float2 v0 = *(const float2*)(Hb + (size_t)sarr[i]*C);
        if constexpr (NORM) {
            v0.x = lrelu_f(gi0*(v0.x-am0)+bt0); v0.y = lrelu_f(gi1*(v0.y-am1)+bt1);
        }
        a0x += v0.x*w0; a0y += v0.y*w0;
    }
    float mins = g_mins[node];
    *(float2*)(AGG + (size_t)node*C + c) =
        make_float2(((a0x+a1x)+(a2x+a3x))*mins, ((a0y+a1y)+(a2y+a3y))*mins);
}

template<int C, bool NORM>
__global__ void magg_k(const float* __restrict__ H, float* __restrict__ AGG,
                       const float* __restrict__ s1p, const float* __restrict__ s2p,
                       const float* __restrict__ gamma,
                       const float* __restrict__ beta,
                       const float* __restrict__ alpha)
{
    magg_body<C, NORM>(blockIdx.x, blockIdx.y, H, AGG, s1p, s2p, gamma, beta, alpha);
}

__device__ __forceinline__
void readout_body(int cb, int yb, const float* __restrict__ Hpre,
                  const float* __restrict__ s1p, const float* __restrict__ s2p,
                  const float* __restrict__ gamma, const float* __restrict__ beta,
                  const float* __restrict__ alpha, int off)
{
    int c = cb*128 + threadIdx.x;                    // 0..511
    int rbase = yb*64;
    int b = rbase >> 10;
    float* block = g_pool + 4*B_*HM_;

    float S1 = s1p[b*HM_ + c];
    float S2 = s2p[b*HM_ + c];
    float mean = S1 * (1.f/M_);
    float am   = alpha[c] * mean;
    float var  = S2*(1.f/M_) - 2.f*am*mean + am*am;
    float gi = gamma[c] * rsqrtf(fmaxf(var, 0.f) + EPS_);
    float bb = beta[c];

    float acc = 0.f;
    const float* Hp = Hpre + (size_t)rbase*HM_ + c;
    #pragma unroll 4
    for (int r = 0; r < 64; r++) {
        float v = Hp[(size_t)r*HM_];
        acc += lrelu_f(gi*(v-am) + bb);
    }
    atomicAdd(&block[b*2*HM_ + off + c], acc);
}

// combined: layer-2 gather (blocks [0,8192)) + layer-1 readout ([8192,8448))
__global__ void __launch_bounds__(128)
k_magg2_ro(const float* __restrict__ HM, float* __restrict__ HMa,
           const float* __restrict__ s1p, const float* __restrict__ s2p,
           const float* __restrict__ gamma, const float* __restrict__ beta,
           const float* __restrict__ alpha)
{
    int bx = blockIdx.x;
    if (bx < B_*M_*2) {
        magg_body<HM_, true>(bx >> 1, bx & 1, HM, HMa, s1p, s2p,
                             gamma, beta, alpha);
    } else {
        int rr = bx - B_*M_*2;                       // 0..255
        readout_body(rr & 3, rr >> 2, HM, s1p, s2p, gamma, beta, alpha, 0);
    }
}

// standalone readout (layer 2)
__global__ void __launch_bounds__(128)
k_readout(const float* __restrict__ Hpre,
          const float* __restrict__ s1p, const float* __restrict__ s2p,
          const float* __restrict__ gamma,
          const float* __restrict__ beta,
          const float* __restrict__ alpha, int off)
{
    readout_body(blockIdx.x, blockIdx.y, Hpre, s1p, s2p, gamma, beta, alpha, off);
}

__global__ void final_kernel(const float* __restrict__ Wc, float* __restrict__ out)
{
    int t = threadIdx.x;
    const float* block = g_pool + 4*B_*HM_;
    float acc[OUT_];
    #pragma unroll
    for (int o=0;o<OUT_;o++) acc[o]=0.f;
    for (int i=t;i<B_*2*HM_;i+=256) {
        float v = lrelu_f(block[i] * (1.f/M_));
        #pragma unroll
        for (int o=0;o<OUT_;o++) acc[o] += v*Wc[(size_t)i*OUT_+o];
    }
    __shared__ float red[OUT_][256];
    #pragma unroll
    for (int o=0;o<OUT_;o++) red[o][t]=acc[o];
    __syncthreads();
    for (int s=128;s>0;s>>=1) {
        if (t<s) {
            #pragma unroll
            for (int o=0;o<OUT_;o++) red[o][t]+=red[o][t+s];
        }
        __syncthreads();
    }
    if (t<OUT_) out[t]=red[t][0];
}

// ---------------- launcher -------------------------------------------------
extern "C" void kernel_launch(void* const* d_in, const int* in_sizes, int n_in,
                              void* d_out, int out_size)
{
    (void)in_sizes; (void)n_in; (void)out_size;
    const float* feats = (const float*)d_in[0];
    const int*   psrc  = (const int*)  d_in[1];
    const int*   pdst  = (const int*)  d_in[2];
    const float* pew   = (const float*)d_in[3];
    const int*   msrc  = (const int*)  d_in[4];
    const int*   mdst  = (const int*)  d_in[5];
    const float* mew   = (const float*)d_in[6];
    const float* Wp1   = (const float*)d_in[7];
    const float* Wp2   = (const float*)d_in[8];
    const float* W_emb = (const float*)d_in[9];
    const float* gp1_g = (const float*)d_in[10];
    const float* gp1_b = (const float*)d_in[11];
    const float* gp1_a = (const float*)d_in[12];
    const float* gp2_g = (const float*)d_in[13];
    const float* gp2_b = (const float*)d_in[14];
    const float* gp2_a = (const float*)d_in[15];
    const float* gm1_g = (const float*)d_in[16];
    const float* gm1_b = (const float*)d_in[17];
    const float* gm1_a = (const float*)d_in[18];
    const float* gm2_g = (const float*)d_in[19];
    const float* gm2_b = (const float*)d_in[20];
    const float* gm2_a = (const float*)d_in[21];
    const float* Wm1   = (const float*)d_in[22];
    const float* Wm2   = (const float*)d_in[23];
    const float* Wc    = (const float*)d_in[24];
    float* out = (float*)d_out;

    float *pR,*pNF,*pNFa,*pHM,*pHMa,*pHM2,*pPool;
    cudaGetSymbolAddress((void**)&pR,   g_R);
    cudaGetSymbolAddress((void**)&pNF,  g_NF);
    cudaGetSymbolAddress((void**)&pNFa, g_NFa);
    cudaGetSymbolAddress((void**)&pHM,  g_HM);
    cudaGetSymbolAddress((void**)&pHMa, g_HMa);
    cudaGetSymbolAddress((void**)&pHM2, g_HM2);
    cudaGetSymbolAddress((void**)&pPool, g_pool);
    float* pS1a = (float*)pPool;
    float* pS2a = pS1a + B_*HM_;
    float* pS1b = pS2a + B_*HM_;
    float* pS2b = pS1b + B_*HM_;

    const int SMG  = (2*64*36 + 2*32*136) * 4;           // 53248 B (64x128 tile)
    const int SMEMB = (2*64*36 + 2*32*264) * 4;          // 86016 B
    cudaFuncSetAttribute(gemm_tf32<64,128,true>,
                         cudaFuncAttributeMaxDynamicSharedMemorySize, SMG);
    cudaFuncSetAttribute(gemm_embed_in,
                         cudaFuncAttributeMaxDynamicSharedMemorySize, SMEMB);
    cudaFuncSetAttribute(k_patch_all,
                         cudaFuncAttributeMaxDynamicSharedMemorySize, SMB_PATCH);

    // ---- patch phase + CSR-A (hidden under patch waves) ----
    k_patch_all<<<P_/2 + B_, 256, SMB_PATCH>>>(
        feats, psrc, pdst, pew, Wp1, Wp2,
        gp1_g, gp1_b, gp1_a, gp2_g, gp2_b, gp2_a, msrc, mdst);

    // ---- embed GEMM + fused instance norm + CSR-B (hidden under embed) ----
    gemm_embed_in<<<64 + B_*8, 256, SMEMB>>>(pR, W_emb, pNF, msrc, mdst, mew);

    // ---- mesh layer 1 ----
    magg_k<RD_,false><<<dim3(B_*M_, 1), 128>>>(
        pNF, pNFa, nullptr, nullptr, nullptr, nullptr, nullptr);
    gemm_tf32<64,128,true><<<(B_*M_/64)*(HM_/128), 256, SMG>>>(
        pNFa, Wm1, pHM, B_*M_, HM_, RD_, pS1a, pS2a);

    // ---- layer-2 gather + layer-1 readout, one launch ----
    k_magg2_ro<<<B_*M_*2 + 256, 128>>>(
        pHM, pHMa, pS1a, pS2a, gm1_g, gm1_b, gm1_a);

    // ---- mesh layer 2 ----
    gemm_tf32<64,128,true><<<(B_*M_/64)*(HM_/128), 256, SMG>>>(
        pHMa, Wm2, pHM2, B_*M_, HM_, HM_, pS1b, pS2b);
    k_readout<<<dim3(HM_/128, B_*M_/64), 128>>>(
        pHM2, pS1b, pS2b, gm2_g, gm2_b, gm2_a, HM_);

    // ---- classifier ----
    final_kernel<<<1, 256>>>(Wc, out);
}